// round 6
// baseline (speedup 1.0000x reference)
#include <cuda_runtime.h>
#include <cuda_bf16.h>
#include <math.h>
#include <stdint.h>

// Problem dims
#define T_  512
#define B_  64
#define E_  300
#define H_  512
#define L_  5
#define G3H 1536
#define M_  (T_*B_)          // 32768

// ---------------------------------------------------------------------------
// Scratch (device globals — no runtime allocation allowed)
// ---------------------------------------------------------------------------
__device__ float g_xp0[(size_t)M_ * G3H];
__device__ float g_xp1[(size_t)M_ * G3H];
__device__ float g_h1 [(size_t)M_ * H_];
__device__ float g_h2 [(size_t)M_ * H_];
// per-producer counters: [layer][group][gidx][pad8]
__device__ unsigned g_ctr2[2 * 8 * 16 * 8];

// ---------------------------------------------------------------------------
// helpers
// ---------------------------------------------------------------------------
__device__ __forceinline__ unsigned long long pk2(float lo, float hi) {
    unsigned long long r;
    asm("mov.b64 %0, {%1, %2};" : "=l"(r) : "f"(lo), "f"(hi));
    return r;
}
__device__ __forceinline__ void fma2(unsigned long long& acc,
                                     unsigned long long a, unsigned long long b) {
    asm("fma.rn.f32x2 %0, %1, %2, %0;" : "+l"(acc) : "l"(a), "l"(b));
}
__device__ __forceinline__ float2 unpk(unsigned long long v) {
    float x, y;
    asm("mov.b64 {%0, %1}, %2;" : "=f"(x), "=f"(y) : "l"(v));
    return make_float2(x, y);
}
__device__ __forceinline__ unsigned ld_acquire(const unsigned* p) {
    unsigned v;
    asm volatile("ld.acquire.gpu.u32 %0, [%1];" : "=r"(v) : "l"(p) : "memory");
    return v;
}
__device__ __forceinline__ void red_release(unsigned* p, unsigned v) {
    asm volatile("red.release.gpu.global.add.u32 [%0], %1;" :: "l"(p), "r"(v) : "memory");
}
__device__ __forceinline__ float sigmoidf_(float x) {
    return 1.0f / (1.0f + __expf(-x));
}
__device__ __forceinline__ float tanhf_(float x) {
    return 1.0f - 2.0f / (__expf(2.0f * x) + 1.0f);
}

union F4U { float4 f; unsigned long long u[2]; };
union F2U { float2 f; unsigned long long u; };

// no-op: keeps the ncu capture ordinal on rec_kernel
__global__ void noop_kernel() {}

__global__ void init_ctr_kernel() {
#pragma unroll
    for (int i = 0; i < 4; ++i)
        g_ctr2[threadIdx.x + i * 512] = 0u;
}

// ---------------------------------------------------------------------------
// Projection GEMM: C[M,1536] = A[M,K] @ W[1536,K]^T + bias
// 128x128 tile, BK=16, 256 threads, 8x8 per thread via f32x2.
// Double-buffered smem: ONE __syncthreads per k-tile.
// ---------------------------------------------------------------------------
template <bool GATHER, int K>
__device__ __forceinline__ void proj_ld(
    const float* __restrict__ Abase, const int* __restrict__ gidx,
    const float* __restrict__ W, int m0, int n0, int k0, int tid,
    float4 (&rA)[2], float4 (&rB)[2])
{
#pragma unroll
    for (int p = 0; p < 2; ++p) {
        int v  = tid + p * 256;
        int mn = v & 127;
        int kq = v >> 7;
        int k  = k0 + kq * 4;
        float4 av = make_float4(0.f, 0.f, 0.f, 0.f);
        float4 bv = make_float4(0.f, 0.f, 0.f, 0.f);
        if (k < K) {
            const float* arow;
            if (GATHER) arow = Abase + (size_t)__ldg(gidx + m0 + mn) * K;
            else        arow = Abase + (size_t)(m0 + mn) * K;
            av = *(const float4*)(arow + k);
            bv = *(const float4*)(W + (size_t)(n0 + mn) * K + k);
        }
        rA[p] = av; rB[p] = bv;
    }
}

template <bool GATHER, int K>
__global__ __launch_bounds__(256) void proj_kernel(
    const float* __restrict__ Aparam, const int* __restrict__ gidx,
    const float* __restrict__ W, const float* __restrict__ bias)
{
    __shared__ float As[2][16][128];
    __shared__ float Bs[2][16][128];

    const float* Abase = GATHER ? Aparam : g_h1;
    float* C = GATHER ? g_xp0 : g_xp1;

    const int tid = threadIdx.x;
    const int tx = tid & 15;
    const int ty = tid >> 4;
    const int m0 = blockIdx.y * 128;
    const int n0 = blockIdx.x * 128;

    unsigned long long acc[4][8];
#pragma unroll
    for (int i = 0; i < 4; ++i)
#pragma unroll
        for (int j = 0; j < 8; ++j) acc[i][j] = 0ull;

    float4 rA[2], rB[2];
    proj_ld<GATHER, K>(Abase, gidx, W, m0, n0, 0, tid, rA, rB);
#pragma unroll
    for (int p = 0; p < 2; ++p) {
        int v  = tid + p * 256;
        int mn = v & 127;
        int kq = v >> 7;
        As[0][kq*4+0][mn] = rA[p].x; As[0][kq*4+1][mn] = rA[p].y;
        As[0][kq*4+2][mn] = rA[p].z; As[0][kq*4+3][mn] = rA[p].w;
        Bs[0][kq*4+0][mn] = rB[p].x; Bs[0][kq*4+1][mn] = rB[p].y;
        Bs[0][kq*4+2][mn] = rB[p].z; Bs[0][kq*4+3][mn] = rB[p].w;
    }
    __syncthreads();

    const int KT = (K + 15) >> 4;
    for (int kt = 0; kt < KT; ++kt) {
        const int cur = kt & 1;
        const int nxt = cur ^ 1;
        if (kt + 1 < KT)
            proj_ld<GATHER, K>(Abase, gidx, W, m0, n0, (kt + 1) << 4, tid, rA, rB);
#pragma unroll
        for (int k = 0; k < 16; ++k) {
            const float* ar = &As[cur][k][ty * 8];
            unsigned long long a0 = *(const unsigned long long*)(ar + 0);
            unsigned long long a1 = *(const unsigned long long*)(ar + 2);
            unsigned long long a2 = *(const unsigned long long*)(ar + 4);
            unsigned long long a3 = *(const unsigned long long*)(ar + 6);
            float4 bv0 = *(const float4*)&Bs[cur][k][tx * 8];
            float4 bv1 = *(const float4*)&Bs[cur][k][tx * 8 + 4];
            unsigned long long b[8];
            b[0] = pk2(bv0.x, bv0.x); b[1] = pk2(bv0.y, bv0.y);
            b[2] = pk2(bv0.z, bv0.z); b[3] = pk2(bv0.w, bv0.w);
            b[4] = pk2(bv1.x, bv1.x); b[5] = pk2(bv1.y, bv1.y);
            b[6] = pk2(bv1.z, bv1.z); b[7] = pk2(bv1.w, bv1.w);
#pragma unroll
            for (int n = 0; n < 8; ++n) {
                fma2(acc[0][n], a0, b[n]);
                fma2(acc[1][n], a1, b[n]);
                fma2(acc[2][n], a2, b[n]);
                fma2(acc[3][n], a3, b[n]);
            }
        }
        if (kt + 1 < KT) {
#pragma unroll
            for (int p = 0; p < 2; ++p) {
                int v  = tid + p * 256;
                int mn = v & 127;
                int kq = v >> 7;
                As[nxt][kq*4+0][mn] = rA[p].x; As[nxt][kq*4+1][mn] = rA[p].y;
                As[nxt][kq*4+2][mn] = rA[p].z; As[nxt][kq*4+3][mn] = rA[p].w;
                Bs[nxt][kq*4+0][mn] = rB[p].x; Bs[nxt][kq*4+1][mn] = rB[p].y;
                Bs[nxt][kq*4+2][mn] = rB[p].z; Bs[nxt][kq*4+3][mn] = rB[p].w;
            }
            __syncthreads();
        }
    }

    float4 bb0 = *(const float4*)(bias + n0 + tx * 8);
    float4 bb1 = *(const float4*)(bias + n0 + tx * 8 + 4);
    float bb[8] = {bb0.x, bb0.y, bb0.z, bb0.w, bb1.x, bb1.y, bb1.z, bb1.w};
#pragma unroll
    for (int j = 0; j < 4; ++j) {
        float lo[8], hi[8];
#pragma unroll
        for (int n = 0; n < 8; ++n) {
            float2 u = unpk(acc[j][n]);
            lo[n] = u.x + bb[n];
            hi[n] = u.y + bb[n];
        }
        int m = m0 + ty * 8 + 2 * j;
        float* c0 = C + (size_t)m       * G3H + n0 + tx * 8;
        float* c1 = C + (size_t)(m + 1) * G3H + n0 + tx * 8;
        *(float4*)(c0)     = make_float4(lo[0], lo[1], lo[2], lo[3]);
        *(float4*)(c0 + 4) = make_float4(lo[4], lo[5], lo[6], lo[7]);
        *(float4*)(c1)     = make_float4(hi[0], hi[1], hi[2], hi[3]);
        *(float4*)(c1 + 4) = make_float4(hi[4], hi[5], hi[6], hi[7]);
    }
}

// ---------------------------------------------------------------------------
// Persistent GRU recurrence — 512 threads / 16 warps (4 per SMSP).
// 128 CTAs = 8 groups x 16 CTAs; group g owns batch rows [8g, 8g+8).
// CTA gidx owns hidden slice [gidx*32, +32); weights SMEM-resident transposed.
// Warp w owns k-slice [w*32, w*32+32) == output of producer CTA w (1:1 wait).
// Reduction: 16 partials folded into red[4] in 4 phases.
// ---------------------------------------------------------------------------
#define WSP_F2    (256 * 96)
#define HS_STRIDE 516
#define HS_F      (8 * HS_STRIDE)
#define RED_F     3072
#define SMEM_REC_BYTES ((WSP_F2 * 2 + HS_F + RED_F + 96) * 4)  // 225792 B

__global__ __launch_bounds__(512, 1) void rec_kernel(
    const float* __restrict__ Whh, const float* __restrict__ bhh, int layer)
{
    extern __shared__ float sm[];
    float2* ws_p = (float2*)sm;                       // [256][96]
    float*  hs   = sm + WSP_F2 * 2;                   // [8][516]
    float*  red  = hs + HS_F;                         // [4][3][8][32]
    float*  sb   = red + RED_F;                       // [96]

    const float* xp = layer ? g_xp1 : g_xp0;
    float*       ys = layer ? g_h2  : g_h1;

    const int tid   = threadIdx.x;
    const int wid   = tid >> 5;            // 0..15 = k-slice (32 k each)
    const int li    = tid & 31;
    const int bid   = blockIdx.x;
    const int group = bid >> 4;
    const int gidx  = bid & 15;
    const int rb    = group * 8;
    const int ibase = gidx * 32;

    unsigned* ctr_base = g_ctr2 + ((layer * 8 + group) * 16) * 8;
    unsigned* my_ctr   = ctr_base + gidx * 8;
    unsigned* p_ctr    = ctr_base + wid * 8;    // producer of this warp's k-slice

    // ---- preload transposed weight slice + bias slice ----
    for (int idx = tid; idx < 96 * 256; idx += 512) {
        int r   = idx >> 8;
        int kk2 = idx & 255;
        int gr  = (r >> 5) * 512 + ibase + (r & 31);
        float2 v = *(const float2*)(Whh + (size_t)gr * 512 + kk2 * 2);
        ws_p[kk2 * 96 + r] = v;
    }
    if (tid < 96) {
        int gr = (tid >> 5) * 512 + ibase + (tid & 31);
        sb[tid] = __ldg(bhh + gr);
    }
    __syncthreads();

    const int kbase = wid * 32;
    const int eb = tid >> 5;               // elementwise batch (tid<256)
    const int ei = tid & 31;
    // staging map: 32 k = 8 float4; lane -> (batch s_b, 2 float4 at s_q*2, s_q*2+1)
    const int s_b = li & 7;
    const int s_q = li >> 3;               // 0..3
    const int slot  = wid & 3;             // reduction slot
    const int phase = wid >> 2;            // reduction phase 0..3

    float h_prev_reg = 0.f;                // h_{t-1} for this thread's output

    for (int t = 0; t < T_; ++t) {
        // ---- prefetch xp for this step (warps 0-7 only; overlaps poll) ----
        float xr = 0.f, xz = 0.f, xn = 0.f;
        if (tid < 256) {
            const float* xrow = xp + ((size_t)t * B_ + rb + eb) * G3H + ibase + ei;
            xr = __ldg(xrow);
            xz = __ldg(xrow + 512);
            xn = __ldg(xrow + 1024);
        }

        // ---- wait for producer of this warp's k-slice, stage it ----
        if (t == 0) {
            float* hd = hs + s_b * HS_STRIDE + kbase + s_q * 8;
            *(float4*)(hd)     = make_float4(0.f, 0.f, 0.f, 0.f);
            *(float4*)(hd + 4) = make_float4(0.f, 0.f, 0.f, 0.f);
        } else {
            unsigned target = (unsigned)t;
            while (ld_acquire(p_ctr) < target) { }
            const float* hp = ys + (size_t)(t - 1) * B_ * H_
                            + (size_t)(rb + s_b) * H_ + kbase + s_q * 8;
            float4 v0 = __ldcg((const float4*)(hp));
            float4 v1 = __ldcg((const float4*)(hp + 4));
            float* hd = hs + s_b * HS_STRIDE + kbase + s_q * 8;
            *(float4*)(hd)     = v0;
            *(float4*)(hd + 4) = v1;
        }

        // ---- matvec over own 32-k slice ----
        unsigned long long acc[3][8];
#pragma unroll
        for (int g = 0; g < 3; ++g)
#pragma unroll
            for (int b = 0; b < 8; ++b) acc[g][b] = 0ull;

#pragma unroll 2
        for (int it = 0; it < 8; ++it) {
            const int k4  = kbase + it * 4;
            const int kk2 = k4 >> 1;
            unsigned long long h01[8], h23[8];
#pragma unroll
            for (int b = 0; b < 8; ++b) {
                F4U hv;
                hv.f = *(const float4*)(hs + b * HS_STRIDE + k4);
                h01[b] = hv.u[0];
                h23[b] = hv.u[1];
            }
#pragma unroll
            for (int g = 0; g < 3; ++g) {
                F2U wa, wb;
                wa.f = ws_p[kk2 * 96 + g * 32 + li];
                wb.f = ws_p[(kk2 + 1) * 96 + g * 32 + li];
#pragma unroll
                for (int b = 0; b < 8; ++b) {
                    fma2(acc[g][b], wa.u, h01[b]);
                    fma2(acc[g][b], wb.u, h23[b]);
                }
            }
        }

        float v[3][8];
#pragma unroll
        for (int g = 0; g < 3; ++g)
#pragma unroll
            for (int b = 0; b < 8; ++b) {
                float2 u = unpk(acc[g][b]);
                v[g][b] = u.x + u.y;
            }

        // ---- fold 16 partials into red[4] over 4 phases ----
#pragma unroll
        for (int p = 0; p < 4; ++p) {
            if (phase == p) {
                if (p == 0) {
#pragma unroll
                    for (int g = 0; g < 3; ++g)
#pragma unroll
                        for (int b = 0; b < 8; ++b)
                            red[((slot * 3 + g) * 8 + b) * 32 + li] = v[g][b];
                } else {
#pragma unroll
                    for (int g = 0; g < 3; ++g)
#pragma unroll
                        for (int b = 0; b < 8; ++b)
                            red[((slot * 3 + g) * 8 + b) * 32 + li] += v[g][b];
                }
            }
            __syncthreads();
        }

        // ---- elementwise (warps 0-7: one output each) ----
        if (tid < 256) {
            float ghr = 0.f, ghz = 0.f, ghn = 0.f;
#pragma unroll
            for (int kq = 0; kq < 4; ++kq) {
                ghr += red[((kq * 3 + 0) * 8 + eb) * 32 + ei];
                ghz += red[((kq * 3 + 1) * 8 + eb) * 32 + ei];
                ghn += red[((kq * 3 + 2) * 8 + eb) * 32 + ei];
            }
            ghr += sb[ei];
            ghz += sb[32 + ei];
            ghn += sb[64 + ei];

            float r = sigmoidf_(xr + ghr);
            float z = sigmoidf_(xz + ghz);
            float n = tanhf_(xn + r * ghn);
            float hnew = n + z * (h_prev_reg - n);
            h_prev_reg = hnew;

            __stcg(ys + ((size_t)t * B_ + rb + eb) * H_ + ibase + ei, hnew);
            __threadfence();
        }

        // ---- release own slice ----
        __syncthreads();
        if (tid == 0) red_release(my_ctr, 1u);
    }
}

// ---------------------------------------------------------------------------
// Pool over batch + FC
// ---------------------------------------------------------------------------
__global__ __launch_bounds__(256) void pool_fc_kernel(
    const float* __restrict__ fcW, const float* __restrict__ fcb,
    float* __restrict__ out)
{
    __shared__ float rbuf[5][256];
    const int t = blockIdx.x;
    const int tid = threadIdx.x;

    float s0 = 0.f, s1 = 0.f;
    const float* base = g_h2 + (size_t)t * B_ * H_ + tid * 2;
#pragma unroll 8
    for (int b = 0; b < B_; ++b) {
        float2 vv = *(const float2*)(base + (size_t)b * H_);
        s0 += vv.x; s1 += vv.y;
    }
    s0 *= (1.0f / 64.0f);
    s1 *= (1.0f / 64.0f);

#pragma unroll
    for (int l = 0; l < L_; ++l)
        rbuf[l][tid] = s0 * __ldg(fcW + l * H_ + tid * 2)
                     + s1 * __ldg(fcW + l * H_ + tid * 2 + 1);
    __syncthreads();

    for (int s = 128; s > 0; s >>= 1) {
        if (tid < s) {
#pragma unroll
            for (int l = 0; l < L_; ++l) rbuf[l][tid] += rbuf[l][tid + s];
        }
        __syncthreads();
    }
    if (tid < L_) out[t * L_ + tid] = rbuf[tid][0] + __ldg(fcb + tid);
}

// ---------------------------------------------------------------------------
// launcher
// ---------------------------------------------------------------------------
extern "C" void kernel_launch(void* const* d_in, const int* in_sizes, int n_in,
                              void* d_out, int out_size) {
    (void)in_sizes; (void)n_in; (void)out_size;
    const int*   texts = (const int*)  d_in[0];
    const float* emb   = (const float*)d_in[1];
    const float* Wih0  = (const float*)d_in[2];
    const float* Whh0  = (const float*)d_in[3];
    const float* bih0  = (const float*)d_in[4];
    const float* bhh0  = (const float*)d_in[5];
    const float* Wih1  = (const float*)d_in[6];
    const float* Whh1  = (const float*)d_in[7];
    const float* bih1  = (const float*)d_in[8];
    const float* bhh1  = (const float*)d_in[9];
    const float* fcW   = (const float*)d_in[10];
    const float* fcb   = (const float*)d_in[11];
    float* out = (float*)d_out;

    cudaFuncSetAttribute(rec_kernel,
                         cudaFuncAttributeMaxDynamicSharedMemorySize,
                         SMEM_REC_BYTES);

    noop_kernel<<<1, 32>>>();            // keeps ncu capture on rec_kernel
    init_ctr_kernel<<<1, 512>>>();
    proj_kernel<true, 300><<<dim3(12, 256), 256>>>(emb, texts, Wih0, bih0);
    rec_kernel<<<128, 512, SMEM_REC_BYTES>>>(Whh0, bhh0, 0);
    proj_kernel<false, 512><<<dim3(12, 256), 256>>>(nullptr, nullptr, Wih1, bih1);
    rec_kernel<<<128, 512, SMEM_REC_BYTES>>>(Whh1, bhh1, 1);
    pool_fc_kernel<<<512, 256>>>(fcW, fcb, out);
}

// round 7
// speedup vs baseline: 1.1604x; 1.1604x over previous
#include <cuda_runtime.h>
#include <cuda_bf16.h>
#include <math.h>
#include <stdint.h>

// Problem dims
#define T_  512
#define B_  64
#define E_  300
#define H_  512
#define L_  5
#define G3H 1536
#define M_  (T_*B_)          // 32768

// ---------------------------------------------------------------------------
// Scratch (device globals — no runtime allocation allowed)
// ---------------------------------------------------------------------------
__device__ float g_xp0[(size_t)M_ * G3H];
__device__ float g_xp1[(size_t)M_ * G3H];
__device__ float g_h1 [(size_t)M_ * H_];
__device__ float g_h2 [(size_t)M_ * H_];
__device__ unsigned g_ctr2[2048];

// ---------------------------------------------------------------------------
// helpers
// ---------------------------------------------------------------------------
__device__ __forceinline__ unsigned long long pk2(float lo, float hi) {
    unsigned long long r;
    asm("mov.b64 %0, {%1, %2};" : "=l"(r) : "f"(lo), "f"(hi));
    return r;
}
__device__ __forceinline__ void fma2(unsigned long long& acc,
                                     unsigned long long a, unsigned long long b) {
    asm("fma.rn.f32x2 %0, %1, %2, %0;" : "+l"(acc) : "l"(a), "l"(b));
}
__device__ __forceinline__ float2 unpk(unsigned long long v) {
    float x, y;
    asm("mov.b64 {%0, %1}, %2;" : "=f"(x), "=f"(y) : "l"(v));
    return make_float2(x, y);
}
__device__ __forceinline__ unsigned ld_acquire(const unsigned* p) {
    unsigned v;
    asm volatile("ld.acquire.gpu.u32 %0, [%1];" : "=r"(v) : "l"(p) : "memory");
    return v;
}
__device__ __forceinline__ void red_release(unsigned* p, unsigned v) {
    asm volatile("red.release.gpu.global.add.u32 [%0], %1;" :: "l"(p), "r"(v) : "memory");
}
__device__ __forceinline__ float sigmoidf_(float x) {
    return 1.0f / (1.0f + __expf(-x));
}
__device__ __forceinline__ float tanhf_(float x) {
    return 1.0f - 2.0f / (__expf(2.0f * x) + 1.0f);
}
__device__ __forceinline__ unsigned smem_u32(const void* p) {
    unsigned a;
    asm("{ .reg .u64 t; cvta.to.shared.u64 t, %1; cvt.u32.u64 %0, t; }"
        : "=r"(a) : "l"(p));
    return a;
}
__device__ __forceinline__ unsigned bf16_bits(float x) {
    __nv_bfloat16 h = __float2bfloat16_rn(x);
    return (unsigned)(reinterpret_cast<__nv_bfloat16_raw&>(h).x);
}
__device__ __forceinline__ float bf16_val(unsigned bits) {
    __nv_bfloat16_raw r; r.x = (unsigned short)bits;
    return __bfloat162float(reinterpret_cast<__nv_bfloat16&>(r));
}
__device__ __forceinline__ void ldsm_x4(unsigned& r0, unsigned& r1,
                                        unsigned& r2, unsigned& r3, unsigned a) {
    asm volatile("ldmatrix.sync.aligned.m8n8.x4.shared.b16 {%0,%1,%2,%3},[%4];"
                 : "=r"(r0), "=r"(r1), "=r"(r2), "=r"(r3) : "r"(a));
}
__device__ __forceinline__ void ldsm_x2(unsigned& r0, unsigned& r1, unsigned a) {
    asm volatile("ldmatrix.sync.aligned.m8n8.x2.shared.b16 {%0,%1},[%2];"
                 : "=r"(r0), "=r"(r1) : "r"(a));
}
__device__ __forceinline__ void mma_bf16(float& d0, float& d1, float& d2, float& d3,
                                         unsigned a0, unsigned a1, unsigned a2, unsigned a3,
                                         unsigned b0, unsigned b1) {
    asm volatile("mma.sync.aligned.m16n8k16.row.col.f32.bf16.bf16.f32 "
                 "{%0,%1,%2,%3},{%4,%5,%6,%7},{%8,%9},{%0,%1,%2,%3};"
                 : "+f"(d0), "+f"(d1), "+f"(d2), "+f"(d3)
                 : "r"(a0), "r"(a1), "r"(a2), "r"(a3), "r"(b0), "r"(b1));
}

union F4U { float4 f; unsigned long long u[2]; };

// no-op: keeps the ncu capture ordinal on rec_kernel
__global__ void noop_kernel() {}

__global__ void init_ctr_kernel() {
#pragma unroll
    for (int i = 0; i < 4; ++i)
        g_ctr2[threadIdx.x + i * 512] = 0u;
}

// ---------------------------------------------------------------------------
// Projection GEMM (unchanged from R5): C[M,1536] = A[M,K] @ W[1536,K]^T + bias
// ---------------------------------------------------------------------------
template <bool GATHER, int K>
__device__ __forceinline__ void proj_ld(
    const float* __restrict__ Abase, const int* __restrict__ gidx,
    const float* __restrict__ W, int m0, int n0, int k0, int tid,
    float4 (&rA)[2], float4 (&rB)[2])
{
#pragma unroll
    for (int p = 0; p < 2; ++p) {
        int v  = tid + p * 256;
        int mn = v & 127;
        int kq = v >> 7;
        int k  = k0 + kq * 4;
        float4 av = make_float4(0.f, 0.f, 0.f, 0.f);
        float4 bv = make_float4(0.f, 0.f, 0.f, 0.f);
        if (k < K) {
            const float* arow;
            if (GATHER) arow = Abase + (size_t)__ldg(gidx + m0 + mn) * K;
            else        arow = Abase + (size_t)(m0 + mn) * K;
            av = *(const float4*)(arow + k);
            bv = *(const float4*)(W + (size_t)(n0 + mn) * K + k);
        }
        rA[p] = av; rB[p] = bv;
    }
}

template <bool GATHER, int K>
__global__ __launch_bounds__(256) void proj_kernel(
    const float* __restrict__ Aparam, const int* __restrict__ gidx,
    const float* __restrict__ W, const float* __restrict__ bias)
{
    __shared__ float As[2][16][128];
    __shared__ float Bs[2][16][128];

    const float* Abase = GATHER ? Aparam : g_h1;
    float* C = GATHER ? g_xp0 : g_xp1;

    const int tid = threadIdx.x;
    const int tx = tid & 15;
    const int ty = tid >> 4;
    const int m0 = blockIdx.y * 128;
    const int n0 = blockIdx.x * 128;

    unsigned long long acc[4][8];
#pragma unroll
    for (int i = 0; i < 4; ++i)
#pragma unroll
        for (int j = 0; j < 8; ++j) acc[i][j] = 0ull;

    float4 rA[2], rB[2];
    proj_ld<GATHER, K>(Abase, gidx, W, m0, n0, 0, tid, rA, rB);
#pragma unroll
    for (int p = 0; p < 2; ++p) {
        int v  = tid + p * 256;
        int mn = v & 127;
        int kq = v >> 7;
        As[0][kq*4+0][mn] = rA[p].x; As[0][kq*4+1][mn] = rA[p].y;
        As[0][kq*4+2][mn] = rA[p].z; As[0][kq*4+3][mn] = rA[p].w;
        Bs[0][kq*4+0][mn] = rB[p].x; Bs[0][kq*4+1][mn] = rB[p].y;
        Bs[0][kq*4+2][mn] = rB[p].z; Bs[0][kq*4+3][mn] = rB[p].w;
    }
    __syncthreads();

    const int KT = (K + 15) >> 4;
    for (int kt = 0; kt < KT; ++kt) {
        const int cur = kt & 1;
        const int nxt = cur ^ 1;
        if (kt + 1 < KT)
            proj_ld<GATHER, K>(Abase, gidx, W, m0, n0, (kt + 1) << 4, tid, rA, rB);
#pragma unroll
        for (int k = 0; k < 16; ++k) {
            const float* ar = &As[cur][k][ty * 8];
            unsigned long long a0 = *(const unsigned long long*)(ar + 0);
            unsigned long long a1 = *(const unsigned long long*)(ar + 2);
            unsigned long long a2 = *(const unsigned long long*)(ar + 4);
            unsigned long long a3 = *(const unsigned long long*)(ar + 6);
            float4 bv0 = *(const float4*)&Bs[cur][k][tx * 8];
            float4 bv1 = *(const float4*)&Bs[cur][k][tx * 8 + 4];
            unsigned long long b[8];
            b[0] = pk2(bv0.x, bv0.x); b[1] = pk2(bv0.y, bv0.y);
            b[2] = pk2(bv0.z, bv0.z); b[3] = pk2(bv0.w, bv0.w);
            b[4] = pk2(bv1.x, bv1.x); b[5] = pk2(bv1.y, bv1.y);
            b[6] = pk2(bv1.z, bv1.z); b[7] = pk2(bv1.w, bv1.w);
#pragma unroll
            for (int n = 0; n < 8; ++n) {
                fma2(acc[0][n], a0, b[n]);
                fma2(acc[1][n], a1, b[n]);
                fma2(acc[2][n], a2, b[n]);
                fma2(acc[3][n], a3, b[n]);
            }
        }
        if (kt + 1 < KT) {
#pragma unroll
            for (int p = 0; p < 2; ++p) {
                int v  = tid + p * 256;
                int mn = v & 127;
                int kq = v >> 7;
                As[nxt][kq*4+0][mn] = rA[p].x; As[nxt][kq*4+1][mn] = rA[p].y;
                As[nxt][kq*4+2][mn] = rA[p].z; As[nxt][kq*4+3][mn] = rA[p].w;
                Bs[nxt][kq*4+0][mn] = rB[p].x; Bs[nxt][kq*4+1][mn] = rB[p].y;
                Bs[nxt][kq*4+2][mn] = rB[p].z; Bs[nxt][kq*4+3][mn] = rB[p].w;
            }
            __syncthreads();
        }
    }

    float4 bb0 = *(const float4*)(bias + n0 + tx * 8);
    float4 bb1 = *(const float4*)(bias + n0 + tx * 8 + 4);
    float bb[8] = {bb0.x, bb0.y, bb0.z, bb0.w, bb1.x, bb1.y, bb1.z, bb1.w};
#pragma unroll
    for (int j = 0; j < 4; ++j) {
        float lo[8], hi[8];
#pragma unroll
        for (int n = 0; n < 8; ++n) {
            float2 u = unpk(acc[j][n]);
            lo[n] = u.x + bb[n];
            hi[n] = u.y + bb[n];
        }
        int m = m0 + ty * 8 + 2 * j;
        float* c0 = C + (size_t)m       * G3H + n0 + tx * 8;
        float* c1 = C + (size_t)(m + 1) * G3H + n0 + tx * 8;
        *(float4*)(c0)     = make_float4(lo[0], lo[1], lo[2], lo[3]);
        *(float4*)(c0 + 4) = make_float4(lo[4], lo[5], lo[6], lo[7]);
        *(float4*)(c1)     = make_float4(hi[0], hi[1], hi[2], hi[3]);
        *(float4*)(c1 + 4) = make_float4(hi[4], hi[5], hi[6], hi[7]);
    }
}

// ---------------------------------------------------------------------------
// Persistent GRU recurrence — tensor-core matvec (mma.sync bf16 split).
// 128 CTAs = 8 groups x 16 CTAs; group g owns batch rows [8g, 8g+8).
// CTA gidx owns hidden slice [gidx*32,+32): gh[96x8] = W[96x512] . h^T[512x8]
// W kept SMEM-resident as bf16 hi/lo (2-way split, 3 HMMA products, fp32 acc).
// 384 threads = 12 warps = 6 m-tiles x 2 k-halves.
// ---------------------------------------------------------------------------
#define WROW    520                       // padded bf16 row stride (1040 B)
#define WH_OFF  0                         // [96][520] bf16  = 99840 B
#define WL_OFF  99840                     // [96][520] bf16
#define HH_OFF  199680                    // [8][520] bf16   = 8320 B
#define HL_OFF  208000                    // [8][520] bf16
#define RED_OFF 216320                    // [2][96][9] f32  = 6912 B
#define SB_OFF  223232                    // [96] f32
#define SMEM_REC_BYTES 223616

__global__ __launch_bounds__(384, 1) void rec_kernel(
    const float* __restrict__ Whh, const float* __restrict__ bhh, int layer)
{
    extern __shared__ char smc[];
    float* red = (float*)(smc + RED_OFF);
    float* sb  = (float*)(smc + SB_OFF);
    const unsigned sbase = smem_u32(smc);

    const float* xp = layer ? g_xp1 : g_xp0;
    float*       ys = layer ? g_h2  : g_h1;

    const int tid   = threadIdx.x;
    const int wid   = tid >> 5;
    const int li    = tid & 31;
    const int bid   = blockIdx.x;
    const int group = bid >> 4;
    const int gidx  = bid & 15;
    const int rb    = group * 8;
    const int ibase = gidx * 32;
    unsigned* ctr = g_ctr2 + (layer * 8 + group) * 32;

    // ---- preload weights (bf16 hi/lo split) + bias ----
    for (int idx = tid; idx < 96 * 256; idx += 384) {
        int r  = idx >> 8;                 // local row 0..95 (= gate*32 + i)
        int kk = (idx & 255) << 1;
        int gr = (r >> 5) * 512 + ibase + (r & 31);
        float2 w = *(const float2*)(Whh + (size_t)gr * 512 + kk);
        unsigned h0 = bf16_bits(w.x), h1 = bf16_bits(w.y);
        unsigned l0 = bf16_bits(w.x - bf16_val(h0));
        unsigned l1 = bf16_bits(w.y - bf16_val(h1));
        *(unsigned*)(smc + WH_OFF + (r * WROW + kk) * 2) = (h1 << 16) | h0;
        *(unsigned*)(smc + WL_OFF + (r * WROW + kk) * 2) = (l1 << 16) | l0;
    }
    if (tid < 96) {
        int gr = (tid >> 5) * 512 + ibase + (tid & 31);
        sb[tid] = __ldg(bhh + gr);
    }
    __syncthreads();

    // MMA warp roles
    const int mt = wid % 6;                // m-tile (rows mt*16..mt*16+15)
    const int kh = wid / 6;                // k-half (0/1), wid<12
    const int k0 = kh * 256;
    // ldmatrix lane addresses (bf16-element offsets, x2 bytes)
    const int la  = li & 15;
    const unsigned aoff = ((mt * 16 + la) * WROW + k0 + ((li >> 4) & 1) * 8) * 2;
    const unsigned boff = (((la & 7) * WROW) + k0 + ((la >> 3) & 1) * 8) * 2;
    const unsigned aAhi = sbase + WH_OFF + aoff;
    const unsigned aAlo = sbase + WL_OFF + aoff;
    const unsigned aBhi = sbase + HH_OFF + boff;
    const unsigned aBlo = sbase + HL_OFF + boff;
    // fragment coords for epilogue
    const int fg  = li >> 2;               // 0..7 row in tile
    const int ft  = li & 3;                // col pair
    // elementwise mapping
    const int eb = tid >> 5;               // batch (tid<256)
    const int ei = tid & 31;

    float h_prev_reg = 0.f;

    for (int t = 0; t < T_; ++t) {
        // ---- xp prefetch (overlaps poll) ----
        float xr = 0.f, xz = 0.f, xn = 0.f;
        if (tid < 256) {
            const float* xrow = xp + ((size_t)t * B_ + rb + eb) * G3H + ibase + ei;
            xr = __ldg(xrow);
            xz = __ldg(xrow + 512);
            xn = __ldg(xrow + 1024);
        }

        // ---- wait + stage h (split to bf16 hi/lo) ----
        if (t == 0) {
            for (int idx = tid; idx < 2048; idx += 384) {
                int b = idx >> 8, kk = (idx & 255) << 1;
                *(unsigned*)(smc + HH_OFF + (b * WROW + kk) * 2) = 0u;
                *(unsigned*)(smc + HL_OFF + (b * WROW + kk) * 2) = 0u;
            }
        } else {
            unsigned target = 16u * (unsigned)t;
            while (ld_acquire(ctr) < target) { }
            const float* hp = ys + (size_t)(t - 1) * B_ * H_ + (size_t)rb * H_;
            for (int idx = tid; idx < 2048; idx += 384) {
                int b = idx >> 8, kk = (idx & 255) << 1;
                float2 v = __ldcg((const float2*)(hp + (size_t)b * H_ + kk));
                unsigned h0 = bf16_bits(v.x), h1 = bf16_bits(v.y);
                unsigned l0 = bf16_bits(v.x - bf16_val(h0));
                unsigned l1 = bf16_bits(v.y - bf16_val(h1));
                *(unsigned*)(smc + HH_OFF + (b * WROW + kk) * 2) = (h1 << 16) | h0;
                *(unsigned*)(smc + HL_OFF + (b * WROW + kk) * 2) = (l1 << 16) | l0;
            }
        }
        __syncthreads();

        // ---- tensor-core matvec: warps 0-11 ----
        if (wid < 12) {
            float d0[4] = {0.f, 0.f, 0.f, 0.f};
            float d1[4] = {0.f, 0.f, 0.f, 0.f};
#pragma unroll 8
            for (int ks = 0; ks < 16; ++ks) {
                const unsigned kb = ks * 32;   // 16 bf16 = 32 B per step
                unsigned ah0, ah1, ah2, ah3, al0, al1, al2, al3;
                unsigned bh0, bh1, bl0, bl1;
                ldsm_x4(ah0, ah1, ah2, ah3, aAhi + kb);
                ldsm_x4(al0, al1, al2, al3, aAlo + kb);
                ldsm_x2(bh0, bh1, aBhi + kb);
                ldsm_x2(bl0, bl1, aBlo + kb);
                float* d = (ks & 1) ? d1 : d0;
                mma_bf16(d[0], d[1], d[2], d[3], ah0, ah1, ah2, ah3, bh0, bh1);
                mma_bf16(d[0], d[1], d[2], d[3], ah0, ah1, ah2, ah3, bl0, bl1);
                mma_bf16(d[0], d[1], d[2], d[3], al0, al1, al2, al3, bh0, bh1);
            }
            // store fragments: c0,c1 = (row fg, cols 2ft,2ft+1); c2,c3 = row fg+8
            float* rk = red + kh * 96 * 9;
            rk[(mt * 16 + fg)     * 9 + 2 * ft    ] = d0[0] + d1[0];
            rk[(mt * 16 + fg)     * 9 + 2 * ft + 1] = d0[1] + d1[1];
            rk[(mt * 16 + fg + 8) * 9 + 2 * ft    ] = d0[2] + d1[2];
            rk[(mt * 16 + fg + 8) * 9 + 2 * ft + 1] = d0[3] + d1[3];
        }
        __syncthreads();

        // ---- elementwise (threads 0-255) ----
        if (tid < 256) {
            float ghr = red[(0 * 32 + ei) * 9 + eb] + red[96 * 9 + (0 * 32 + ei) * 9 + eb];
            float ghz = red[(32 + ei) * 9 + eb]     + red[96 * 9 + (32 + ei) * 9 + eb];
            float ghn = red[(64 + ei) * 9 + eb]     + red[96 * 9 + (64 + ei) * 9 + eb];
            ghr += sb[ei];
            ghz += sb[32 + ei];
            ghn += sb[64 + ei];

            float r = sigmoidf_(xr + ghr);
            float z = sigmoidf_(xz + ghz);
            float n = tanhf_(xn + r * ghn);
            float hnew = n + z * (h_prev_reg - n);
            h_prev_reg = hnew;

            __stcg(ys + ((size_t)t * B_ + rb + eb) * H_ + ibase + ei, hnew);
        }

        // ---- release (bar.sync orders all stores before tid0's release) ----
        __syncthreads();
        if (tid == 0) red_release(ctr, 1u);
    }
}

// ---------------------------------------------------------------------------
// Pool over batch + FC
// ---------------------------------------------------------------------------
__global__ __launch_bounds__(256) void pool_fc_kernel(
    const float* __restrict__ fcW, const float* __restrict__ fcb,
    float* __restrict__ out)
{
    __shared__ float rbuf[5][256];
    const int t = blockIdx.x;
    const int tid = threadIdx.x;

    float s0 = 0.f, s1 = 0.f;
    const float* base = g_h2 + (size_t)t * B_ * H_ + tid * 2;
#pragma unroll 8
    for (int b = 0; b < B_; ++b) {
        float2 vv = *(const float2*)(base + (size_t)b * H_);
        s0 += vv.x; s1 += vv.y;
    }
    s0 *= (1.0f / 64.0f);
    s1 *= (1.0f / 64.0f);

#pragma unroll
    for (int l = 0; l < L_; ++l)
        rbuf[l][tid] = s0 * __ldg(fcW + l * H_ + tid * 2)
                     + s1 * __ldg(fcW + l * H_ + tid * 2 + 1);
    __syncthreads();

    for (int s = 128; s > 0; s >>= 1) {
        if (tid < s) {
#pragma unroll
            for (int l = 0; l < L_; ++l) rbuf[l][tid] += rbuf[l][tid + s];
        }
        __syncthreads();
    }
    if (tid < L_) out[t * L_ + tid] = rbuf[tid][0] + __ldg(fcb + tid);
}

// ---------------------------------------------------------------------------
// launcher
// ---------------------------------------------------------------------------
extern "C" void kernel_launch(void* const* d_in, const int* in_sizes, int n_in,
                              void* d_out, int out_size) {
    (void)in_sizes; (void)n_in; (void)out_size;
    const int*   texts = (const int*)  d_in[0];
    const float* emb   = (const float*)d_in[1];
    const float* Wih0  = (const float*)d_in[2];
    const float* Whh0  = (const float*)d_in[3];
    const float* bih0  = (const float*)d_in[4];
    const float* bhh0  = (const float*)d_in[5];
    const float* Wih1  = (const float*)d_in[6];
    const float* Whh1  = (const float*)d_in[7];
    const float* bih1  = (const float*)d_in[8];
    const float* bhh1  = (const float*)d_in[9];
    const float* fcW   = (const float*)d_in[10];
    const float* fcb   = (const float*)d_in[11];
    float* out = (float*)d_out;

    cudaFuncSetAttribute(rec_kernel,
                         cudaFuncAttributeMaxDynamicSharedMemorySize,
                         SMEM_REC_BYTES);

    noop_kernel<<<1, 32>>>();            // keeps ncu capture on rec_kernel
    init_ctr_kernel<<<1, 512>>>();
    proj_kernel<true, 300><<<dim3(12, 256), 256>>>(emb, texts, Wih0, bih0);
    rec_kernel<<<128, 384, SMEM_REC_BYTES>>>(Whh0, bhh0, 0);
    proj_kernel<false, 512><<<dim3(12, 256), 256>>>(nullptr, nullptr, Wih1, bih1);
    rec_kernel<<<128, 384, SMEM_REC_BYTES>>>(Whh1, bhh1, 1);
    pool_fc_kernel<<<512, 256>>>(fcW, fcb, out);
}

// round 8
// speedup vs baseline: 1.3772x; 1.1868x over previous
#include <cuda_runtime.h>
#include <cuda_bf16.h>
#include <math.h>
#include <stdint.h>

// Problem dims
#define T_  512
#define B_  64
#define E_  300
#define H_  512
#define L_  5
#define G3H 1536
#define M_  (T_*B_)          // 32768
#define V_  30000
#define EP_ 304              // E padded to k16 multiple

// ---------------------------------------------------------------------------
// Scratch (device globals — no runtime allocation allowed)
// ---------------------------------------------------------------------------
__device__ float g_xp0[(size_t)M_ * G3H];
__device__ float g_xp1[(size_t)M_ * G3H];
__device__ float g_h2 [(size_t)M_ * H_];
__device__ unsigned g_ctr2[2048];
// bf16 hi/lo split operands
__device__ unsigned short g_embh[(size_t)V_ * EP_];
__device__ unsigned short g_embl[(size_t)V_ * EP_];
__device__ unsigned short g_w0h[(size_t)G3H * EP_];
__device__ unsigned short g_w0l[(size_t)G3H * EP_];
__device__ unsigned short g_w1h[(size_t)G3H * H_];
__device__ unsigned short g_w1l[(size_t)G3H * H_];
__device__ unsigned short g_hbh[2 * (size_t)M_ * H_];
__device__ unsigned short g_hbl[2 * (size_t)M_ * H_];

// ---------------------------------------------------------------------------
// helpers
// ---------------------------------------------------------------------------
__device__ __forceinline__ unsigned ld_acquire(const unsigned* p) {
    unsigned v;
    asm volatile("ld.acquire.gpu.u32 %0, [%1];" : "=r"(v) : "l"(p) : "memory");
    return v;
}
__device__ __forceinline__ void red_release(unsigned* p, unsigned v) {
    asm volatile("red.release.gpu.global.add.u32 [%0], %1;" :: "l"(p), "r"(v) : "memory");
}
__device__ __forceinline__ float sigmoidf_(float x) {
    return 1.0f / (1.0f + __expf(-x));
}
__device__ __forceinline__ float tanhf_(float x) {
    return 1.0f - 2.0f / (__expf(2.0f * x) + 1.0f);
}
__device__ __forceinline__ unsigned smem_u32(const void* p) {
    unsigned a;
    asm("{ .reg .u64 t; cvta.to.shared.u64 t, %1; cvt.u32.u64 %0, t; }"
        : "=r"(a) : "l"(p));
    return a;
}
__device__ __forceinline__ unsigned bf16_bits(float x) {
    __nv_bfloat16 h = __float2bfloat16_rn(x);
    return (unsigned)(reinterpret_cast<__nv_bfloat16_raw&>(h).x);
}
__device__ __forceinline__ float bf16_val(unsigned bits) {
    __nv_bfloat16_raw r; r.x = (unsigned short)bits;
    return __bfloat162float(reinterpret_cast<__nv_bfloat16&>(r));
}
__device__ __forceinline__ void ldsm_x4(unsigned& r0, unsigned& r1,
                                        unsigned& r2, unsigned& r3, unsigned a) {
    asm volatile("ldmatrix.sync.aligned.m8n8.x4.shared.b16 {%0,%1,%2,%3},[%4];"
                 : "=r"(r0), "=r"(r1), "=r"(r2), "=r"(r3) : "r"(a));
}
__device__ __forceinline__ void ldsm_x2(unsigned& r0, unsigned& r1, unsigned a) {
    asm volatile("ldmatrix.sync.aligned.m8n8.x2.shared.b16 {%0,%1},[%2];"
                 : "=r"(r0), "=r"(r1) : "r"(a));
}
__device__ __forceinline__ void mma_bf16(float& d0, float& d1, float& d2, float& d3,
                                         unsigned a0, unsigned a1, unsigned a2, unsigned a3,
                                         unsigned b0, unsigned b1) {
    asm volatile("mma.sync.aligned.m16n8k16.row.col.f32.bf16.bf16.f32 "
                 "{%0,%1,%2,%3},{%4,%5,%6,%7},{%8,%9},{%0,%1,%2,%3};"
                 : "+f"(d0), "+f"(d1), "+f"(d2), "+f"(d3)
                 : "r"(a0), "r"(a1), "r"(a2), "r"(a3), "r"(b0), "r"(b1));
}

__global__ void init_ctr_kernel() {
#pragma unroll
    for (int i = 0; i < 4; ++i)
        g_ctr2[threadIdx.x + i * 512] = 0u;
}

// ---------------------------------------------------------------------------
// fp32 -> bf16 hi/lo split with zero k-padding.
// sel: 0=emb[V,300]->[V,304], 1=Wih0[1536,300]->[1536,304], 2=Wih1[1536,512]
// ---------------------------------------------------------------------------
__global__ void cvt_split_kernel(int sel, const float* __restrict__ src) {
    int rows, ks, kd;
    unsigned short *dh, *dl;
    if (sel == 0)      { rows = V_;  ks = E_; kd = EP_; dh = g_embh; dl = g_embl; }
    else if (sel == 1) { rows = G3H; ks = E_; kd = EP_; dh = g_w0h;  dl = g_w0l; }
    else               { rows = G3H; ks = H_; kd = H_;  dh = g_w1h;  dl = g_w1l; }

    size_t tot = (size_t)rows * kd;
    for (size_t idx = blockIdx.x * blockDim.x + threadIdx.x; idx < tot;
         idx += (size_t)gridDim.x * blockDim.x) {
        int r = (int)(idx / kd);
        int c = (int)(idx - (size_t)r * kd);
        float v = (c < ks) ? src[(size_t)r * ks + c] : 0.f;
        unsigned h = bf16_bits(v);
        float rem = v - bf16_val(h);
        dh[idx] = (unsigned short)h;
        dl[idx] = (unsigned short)bf16_bits(rem);
    }
}

// ---------------------------------------------------------------------------
// Tensor-core projection GEMM: C[M,1536] = A[M,K] @ W[1536,K]^T + bias
// A, W in bf16 hi/lo (3-product split). 128x128 tile, BK=16, 256 threads,
// 8 warps (4m x 2n), warp tile 32x64, double-buffered smem.
// SRC=0: A = emb gather (K=304) -> g_xp0;  SRC=1: A = g_hb layer0 (K=512) -> g_xp1
// ---------------------------------------------------------------------------
#define PROW 24                          // padded smem row stride (bf16 elems)
#define PMAT 6144                        // 128*24*2 bytes per matrix
#define PSTG 24576                       // 4 matrices per stage
#define SMEM_PROJ (2 * PSTG)             // 49152 B

template <int K, int SRC>
__global__ __launch_bounds__(256, 1) void proj_mma(
    const int* __restrict__ gidx, const float* __restrict__ bias)
{
    extern __shared__ __align__(16) char smp[];
    const unsigned short* Ah = (SRC == 0) ? g_embh : g_hbh;
    const unsigned short* Al = (SRC == 0) ? g_embl : g_hbl;
    const unsigned short* Wh = (SRC == 0) ? g_w0h : g_w1h;
    const unsigned short* Wl = (SRC == 0) ? g_w0l : g_w1l;
    float* C = (SRC == 0) ? g_xp0 : g_xp1;

    const int tid = threadIdx.x;
    const int li  = tid & 31;
    const int w   = tid >> 5;
    const int wm  = w >> 1;               // 0..3
    const int wn  = w & 1;                // 0..1
    const int m0  = blockIdx.y * 128;
    const int n0  = blockIdx.x * 128;
    const unsigned sbase = smem_u32(smp);

    // loader: thread -> (row, k-half)
    const int lrow  = tid >> 1;
    const int lhalf = tid & 1;
    size_t arow;
    if (SRC == 0) arow = (size_t)__ldg(gidx + m0 + lrow) * K;
    else          arow = (size_t)(m0 + lrow) * K;
    const size_t brow = (size_t)(n0 + lrow) * K;
    const unsigned sst = (unsigned)(lrow * PROW + lhalf * 8) * 2;

    float acc[2][8][4];
#pragma unroll
    for (int a = 0; a < 2; ++a)
#pragma unroll
        for (int b = 0; b < 8; ++b)
#pragma unroll
            for (int c = 0; c < 4; ++c) acc[a][b][c] = 0.f;

    const int KT = K / 16;
    uint4 rAh, rAl, rBh, rBl;
    {
        const int k0 = lhalf * 8;
        rAh = *(const uint4*)(Ah + arow + k0);
        rAl = *(const uint4*)(Al + arow + k0);
        rBh = *(const uint4*)(Wh + brow + k0);
        rBl = *(const uint4*)(Wl + brow + k0);
        *(uint4*)(smp + 0 * PMAT + sst) = rAh;
        *(uint4*)(smp + 1 * PMAT + sst) = rAl;
        *(uint4*)(smp + 2 * PMAT + sst) = rBh;
        *(uint4*)(smp + 3 * PMAT + sst) = rBl;
    }
    __syncthreads();

    const unsigned aoff = (unsigned)((wm * 32 + (li & 15)) * PROW + (li >> 4) * 8) * 2;
    const unsigned boff = (unsigned)((wn * 64 + (li & 15)) * PROW + (li >> 4) * 8) * 2;

    for (int kt = 0; kt < KT; ++kt) {
        const unsigned sb0 = sbase + (unsigned)(kt & 1) * PSTG;
        if (kt + 1 < KT) {
            const int k0 = (kt + 1) * 16 + lhalf * 8;
            rAh = *(const uint4*)(Ah + arow + k0);
            rAl = *(const uint4*)(Al + arow + k0);
            rBh = *(const uint4*)(Wh + brow + k0);
            rBl = *(const uint4*)(Wl + brow + k0);
        }

        unsigned aH[2][4], aL[2][4];
#pragma unroll
        for (int mt = 0; mt < 2; ++mt) {
            ldsm_x4(aH[mt][0], aH[mt][1], aH[mt][2], aH[mt][3],
                    sb0 + 0 * PMAT + aoff + mt * 768);
            ldsm_x4(aL[mt][0], aL[mt][1], aL[mt][2], aL[mt][3],
                    sb0 + 1 * PMAT + aoff + mt * 768);
        }
#pragma unroll
        for (int ng = 0; ng < 4; ++ng) {
            unsigned bh[4], bl[4];
            ldsm_x4(bh[0], bh[1], bh[2], bh[3], sb0 + 2 * PMAT + boff + ng * 768);
            ldsm_x4(bl[0], bl[1], bl[2], bl[3], sb0 + 3 * PMAT + boff + ng * 768);
#pragma unroll
            for (int mt = 0; mt < 2; ++mt) {
                float* d0 = acc[mt][2 * ng];
                mma_bf16(d0[0], d0[1], d0[2], d0[3],
                         aH[mt][0], aH[mt][1], aH[mt][2], aH[mt][3], bh[0], bh[2]);
                mma_bf16(d0[0], d0[1], d0[2], d0[3],
                         aH[mt][0], aH[mt][1], aH[mt][2], aH[mt][3], bl[0], bl[2]);
                mma_bf16(d0[0], d0[1], d0[2], d0[3],
                         aL[mt][0], aL[mt][1], aL[mt][2], aL[mt][3], bh[0], bh[2]);
                float* d1 = acc[mt][2 * ng + 1];
                mma_bf16(d1[0], d1[1], d1[2], d1[3],
                         aH[mt][0], aH[mt][1], aH[mt][2], aH[mt][3], bh[1], bh[3]);
                mma_bf16(d1[0], d1[1], d1[2], d1[3],
                         aH[mt][0], aH[mt][1], aH[mt][2], aH[mt][3], bl[1], bl[3]);
                mma_bf16(d1[0], d1[1], d1[2], d1[3],
                         aL[mt][0], aL[mt][1], aL[mt][2], aL[mt][3], bh[1], bh[3]);
            }
        }
        if (kt + 1 < KT) {
            char* nb = smp + ((kt & 1) ^ 1) * PSTG;
            *(uint4*)(nb + 0 * PMAT + sst) = rAh;
            *(uint4*)(nb + 1 * PMAT + sst) = rAl;
            *(uint4*)(nb + 2 * PMAT + sst) = rBh;
            *(uint4*)(nb + 3 * PMAT + sst) = rBl;
            __syncthreads();
        }
    }

    // epilogue: fragment (fg, 2*ft) layout
    const int fg = li >> 2;
    const int ft = li & 3;
#pragma unroll
    for (int mt = 0; mt < 2; ++mt) {
#pragma unroll
        for (int nt = 0; nt < 8; ++nt) {
            const int row = m0 + wm * 32 + mt * 16 + fg;
            const int col = n0 + wn * 64 + nt * 8 + 2 * ft;
            const float b0 = __ldg(bias + col);
            const float b1 = __ldg(bias + col + 1);
            float* c0 = C + (size_t)row * G3H + col;
            float* c1 = C + (size_t)(row + 8) * G3H + col;
            *(float2*)c0 = make_float2(acc[mt][nt][0] + b0, acc[mt][nt][1] + b1);
            *(float2*)c1 = make_float2(acc[mt][nt][2] + b0, acc[mt][nt][3] + b1);
        }
    }
}

// ---------------------------------------------------------------------------
// Persistent GRU recurrence — tensor-core matvec (mma.sync bf16 split).
// 128 CTAs = 8 groups x 16 CTAs; group g owns batch rows [8g, 8g+8).
// CTA gidx owns hidden slice [gidx*32,+32). h exchanged as bf16 hi/lo via L2.
// Single-thread poll + bar broadcast (de-contended).
// ---------------------------------------------------------------------------
#define WROW    520
#define WH_OFF  0
#define WL_OFF  99840
#define HH_OFF  199680
#define HL_OFF  208000
#define RED_OFF 216320
#define SB_OFF  223232
#define SMEM_REC_BYTES 223616

__global__ __launch_bounds__(384, 1) void rec_kernel(
    const float* __restrict__ Whh, const float* __restrict__ bhh, int layer)
{
    extern __shared__ char smc[];
    float* red = (float*)(smc + RED_OFF);
    float* sb  = (float*)(smc + SB_OFF);
    const unsigned sbase = smem_u32(smc);

    const float* xp = layer ? g_xp1 : g_xp0;

    const int tid   = threadIdx.x;
    const int wid   = tid >> 5;
    const int li    = tid & 31;
    const int bid   = blockIdx.x;
    const int group = bid >> 4;
    const int gidx  = bid & 15;
    const int rb    = group * 8;
    const int ibase = gidx * 32;
    unsigned* ctr = g_ctr2 + (layer * 8 + group) * 32;

    unsigned short* hbh = g_hbh + (size_t)layer * M_ * H_;
    unsigned short* hbl = g_hbl + (size_t)layer * M_ * H_;

    // ---- preload weights (bf16 hi/lo split) + bias ----
    for (int idx = tid; idx < 96 * 256; idx += 384) {
        int r  = idx >> 8;
        int kk = (idx & 255) << 1;
        int gr = (r >> 5) * 512 + ibase + (r & 31);
        float2 wv = *(const float2*)(Whh + (size_t)gr * 512 + kk);
        unsigned h0 = bf16_bits(wv.x), h1 = bf16_bits(wv.y);
        unsigned l0 = bf16_bits(wv.x - bf16_val(h0));
        unsigned l1 = bf16_bits(wv.y - bf16_val(h1));
        *(unsigned*)(smc + WH_OFF + (r * WROW + kk) * 2) = (h1 << 16) | h0;
        *(unsigned*)(smc + WL_OFF + (r * WROW + kk) * 2) = (l1 << 16) | l0;
    }
    if (tid < 96) {
        int gr = (tid >> 5) * 512 + ibase + (tid & 31);
        sb[tid] = __ldg(bhh + gr);
    }
    __syncthreads();

    // MMA warp roles
    const int mt = wid % 6;
    const int kh = wid / 6;
    const int k0 = kh * 256;
    const int la = li & 15;
    const unsigned aoff = ((mt * 16 + la) * WROW + k0 + ((li >> 4) & 1) * 8) * 2;
    const unsigned boff = (((la & 7) * WROW) + k0 + ((la >> 3) & 1) * 8) * 2;
    const unsigned aAhi = sbase + WH_OFF + aoff;
    const unsigned aAlo = sbase + WL_OFF + aoff;
    const unsigned aBhi = sbase + HH_OFF + boff;
    const unsigned aBlo = sbase + HL_OFF + boff;
    const int fg = li >> 2;
    const int ft = li & 3;
    const int eb = tid >> 5;
    const int ei = tid & 31;

    float h_prev_reg = 0.f;

    for (int t = 0; t < T_; ++t) {
        // ---- xp prefetch (overlaps poll) ----
        float xr = 0.f, xz = 0.f, xn = 0.f;
        if (tid < 256) {
            const float* xrow = xp + ((size_t)t * B_ + rb + eb) * G3H + ibase + ei;
            xr = __ldg(xrow);
            xz = __ldg(xrow + 512);
            xn = __ldg(xrow + 1024);
        }

        // ---- single-thread poll, bar broadcast, then stage ----
        if (t == 0) {
            for (int idx = tid; idx < 2048; idx += 384) {
                int b = idx >> 8, kk = (idx & 255) << 1;
                *(unsigned*)(smc + HH_OFF + (b * WROW + kk) * 2) = 0u;
                *(unsigned*)(smc + HL_OFF + (b * WROW + kk) * 2) = 0u;
            }
        } else {
            if (tid == 0) {
                unsigned target = 16u * (unsigned)t;
                while (ld_acquire(ctr) < target) { }
            }
            __syncthreads();
            const size_t base = ((size_t)(t - 1) * B_ + rb) * H_;
            for (int idx = tid; idx < 2048; idx += 384) {
                int b = idx >> 8, kk = (idx & 255) << 1;
                unsigned vh = __ldcg((const unsigned*)(hbh + base + (size_t)b * H_ + kk));
                unsigned vl = __ldcg((const unsigned*)(hbl + base + (size_t)b * H_ + kk));
                *(unsigned*)(smc + HH_OFF + (b * WROW + kk) * 2) = vh;
                *(unsigned*)(smc + HL_OFF + (b * WROW + kk) * 2) = vl;
            }
        }
        __syncthreads();

        // ---- tensor-core matvec: warps 0-11 ----
        if (wid < 12) {
            float d0[4] = {0.f, 0.f, 0.f, 0.f};
            float d1[4] = {0.f, 0.f, 0.f, 0.f};
#pragma unroll 8
            for (int ks = 0; ks < 16; ++ks) {
                const unsigned kb = ks * 32;
                unsigned ah0, ah1, ah2, ah3, al0, al1, al2, al3;
                unsigned bh0, bh1, bl0, bl1;
                ldsm_x4(ah0, ah1, ah2, ah3, aAhi + kb);
                ldsm_x4(al0, al1, al2, al3, aAlo + kb);
                ldsm_x2(bh0, bh1, aBhi + kb);
                ldsm_x2(bl0, bl1, aBlo + kb);
                float* d = (ks & 1) ? d1 : d0;
                mma_bf16(d[0], d[1], d[2], d[3], ah0, ah1, ah2, ah3, bh0, bh1);
                mma_bf16(d[0], d[1], d[2], d[3], ah0, ah1, ah2, ah3, bl0, bl1);
                mma_bf16(d[0], d[1], d[2], d[3], al0, al1, al2, al3, bh0, bh1);
            }
            float* rk = red + kh * 96 * 9;
            rk[(mt * 16 + fg)     * 9 + 2 * ft    ] = d0[0] + d1[0];
            rk[(mt * 16 + fg)     * 9 + 2 * ft + 1] = d0[1] + d1[1];
            rk[(mt * 16 + fg + 8) * 9 + 2 * ft    ] = d0[2] + d1[2];
            rk[(mt * 16 + fg + 8) * 9 + 2 * ft + 1] = d0[3] + d1[3];
        }
        __syncthreads();

        // ---- elementwise (threads 0-255) ----
        if (tid < 256) {
            float ghr = red[(ei) * 9 + eb]      + red[96 * 9 + (ei) * 9 + eb];
            float ghz = red[(32 + ei) * 9 + eb] + red[96 * 9 + (32 + ei) * 9 + eb];
            float ghn = red[(64 + ei) * 9 + eb] + red[96 * 9 + (64 + ei) * 9 + eb];
            ghr += sb[ei];
            ghz += sb[32 + ei];
            ghn += sb[64 + ei];

            float r = sigmoidf_(xr + ghr);
            float z = sigmoidf_(xz + ghz);
            float n = tanhf_(xn + r * ghn);
            float hnew = n + z * (h_prev_reg - n);
            h_prev_reg = hnew;

            const size_t off = ((size_t)t * B_ + rb + eb) * H_ + ibase + ei;
            unsigned hb = bf16_bits(hnew);
            float rem = hnew - bf16_val(hb);
            hbh[off] = (unsigned short)hb;
            hbl[off] = (unsigned short)bf16_bits(rem);
            if (layer) __stcg(g_h2 + off, hnew);
        }

        // ---- release ----
        __syncthreads();
        if (tid == 0) red_release(ctr, 1u);
    }
}

// ---------------------------------------------------------------------------
// Pool over batch + FC
// ---------------------------------------------------------------------------
__global__ __launch_bounds__(256) void pool_fc_kernel(
    const float* __restrict__ fcW, const float* __restrict__ fcb,
    float* __restrict__ out)
{
    __shared__ float rbuf[5][256];
    const int t = blockIdx.x;
    const int tid = threadIdx.x;

    float s0 = 0.f, s1 = 0.f;
    const float* base = g_h2 + (size_t)t * B_ * H_ + tid * 2;
#pragma unroll 8
    for (int b = 0; b < B_; ++b) {
        float2 vv = *(const float2*)(base + (size_t)b * H_);
        s0 += vv.x; s1 += vv.y;
    }
    s0 *= (1.0f / 64.0f);
    s1 *= (1.0f / 64.0f);

#pragma unroll
    for (int l = 0; l < L_; ++l)
        rbuf[l][tid] = s0 * __ldg(fcW + l * H_ + tid * 2)
                     + s1 * __ldg(fcW + l * H_ + tid * 2 + 1);
    __syncthreads();

    for (int s = 128; s > 0; s >>= 1) {
        if (tid < s) {
#pragma unroll
            for (int l = 0; l < L_; ++l) rbuf[l][tid] += rbuf[l][tid + s];
        }
        __syncthreads();
    }
    if (tid < L_) out[t * L_ + tid] = rbuf[tid][0] + __ldg(fcb + tid);
}

// ---------------------------------------------------------------------------
// launcher
// ---------------------------------------------------------------------------
extern "C" void kernel_launch(void* const* d_in, const int* in_sizes, int n_in,
                              void* d_out, int out_size) {
    (void)in_sizes; (void)n_in; (void)out_size;
    const int*   texts = (const int*)  d_in[0];
    const float* emb   = (const float*)d_in[1];
    const float* Wih0  = (const float*)d_in[2];
    const float* Whh0  = (const float*)d_in[3];
    const float* bih0  = (const float*)d_in[4];
    const float* bhh0  = (const float*)d_in[5];
    const float* Wih1  = (const float*)d_in[6];
    const float* Whh1  = (const float*)d_in[7];
    const float* bih1  = (const float*)d_in[8];
    const float* bhh1  = (const float*)d_in[9];
    const float* fcW   = (const float*)d_in[10];
    const float* fcb   = (const float*)d_in[11];
    float* out = (float*)d_out;

    cudaFuncSetAttribute(rec_kernel,
                         cudaFuncAttributeMaxDynamicSharedMemorySize,
                         SMEM_REC_BYTES);
    cudaFuncSetAttribute(proj_mma<EP_, 0>,
                         cudaFuncAttributeMaxDynamicSharedMemorySize, SMEM_PROJ);
    cudaFuncSetAttribute(proj_mma<H_, 1>,
                         cudaFuncAttributeMaxDynamicSharedMemorySize, SMEM_PROJ);

    init_ctr_kernel<<<1, 512>>>();
    cvt_split_kernel<<<2048, 256>>>(0, emb);
    cvt_split_kernel<<<512, 256>>>(1, Wih0);
    cvt_split_kernel<<<512, 256>>>(2, Wih1);
    proj_mma<EP_, 0><<<dim3(12, 256), 256, SMEM_PROJ>>>(texts, bih0);
    rec_kernel<<<128, 384, SMEM_REC_BYTES>>>(Whh0, bhh0, 0);
    proj_mma<H_, 1><<<dim3(12, 256), 256, SMEM_PROJ>>>(nullptr, bih1);
    rec_kernel<<<128, 384, SMEM_REC_BYTES>>>(Whh1, bhh1, 1);
    pool_fc_kernel<<<512, 256>>>(fcW, fcb, out);
}

// round 10
// speedup vs baseline: 1.4716x; 1.0686x over previous
#include <cuda_runtime.h>
#include <cuda_bf16.h>
#include <math.h>
#include <stdint.h>

// Problem dims
#define T_  512
#define B_  64
#define E_  300
#define H_  512
#define L_  5
#define G3H 1536
#define M_  (T_*B_)          // 32768
#define V_  30000
#define EP_ 304              // E padded to k16 multiple

// ---------------------------------------------------------------------------
// Scratch (device globals — no runtime allocation allowed)
// ---------------------------------------------------------------------------
__device__ float g_xp0[(size_t)M_ * G3H];
__device__ float g_xp1[(size_t)M_ * G3H];
__device__ float g_h2 [(size_t)M_ * H_];
__device__ unsigned g_ctr2[2048];
// bf16 hi/lo split operands
__device__ unsigned short g_embh[(size_t)V_ * EP_];
__device__ unsigned short g_embl[(size_t)V_ * EP_];
__device__ unsigned short g_w0h[(size_t)G3H * EP_];
__device__ unsigned short g_w0l[(size_t)G3H * EP_];
__device__ unsigned short g_w1h[(size_t)G3H * H_];
__device__ unsigned short g_w1l[(size_t)G3H * H_];
__device__ unsigned short g_hbh[2 * (size_t)M_ * H_];
__device__ unsigned short g_hbl[2 * (size_t)M_ * H_];

// ---------------------------------------------------------------------------
// helpers
// ---------------------------------------------------------------------------
__device__ __forceinline__ unsigned ld_acquire(const unsigned* p) {
    unsigned v;
    asm volatile("ld.acquire.gpu.u32 %0, [%1];" : "=r"(v) : "l"(p) : "memory");
    return v;
}
__device__ __forceinline__ void red_release(unsigned* p, unsigned v) {
    asm volatile("red.release.gpu.global.add.u32 [%0], %1;" :: "l"(p), "r"(v) : "memory");
}
__device__ __forceinline__ float sigmoidf_(float x) {
    return 1.0f / (1.0f + __expf(-x));
}
__device__ __forceinline__ float tanhf_(float x) {
    return 1.0f - 2.0f / (__expf(2.0f * x) + 1.0f);
}
__device__ __forceinline__ unsigned smem_u32(const void* p) {
    unsigned a;
    asm("{ .reg .u64 t; cvta.to.shared.u64 t, %1; cvt.u32.u64 %0, t; }"
        : "=r"(a) : "l"(p));
    return a;
}
__device__ __forceinline__ unsigned bf16_bits(float x) {
    __nv_bfloat16 h = __float2bfloat16_rn(x);
    return (unsigned)(reinterpret_cast<__nv_bfloat16_raw&>(h).x);
}
__device__ __forceinline__ float bf16_val(unsigned bits) {
    __nv_bfloat16_raw r; r.x = (unsigned short)bits;
    return __bfloat162float(reinterpret_cast<__nv_bfloat16&>(r));
}
__device__ __forceinline__ void ldsm_x4(unsigned& r0, unsigned& r1,
                                        unsigned& r2, unsigned& r3, unsigned a) {
    asm volatile("ldmatrix.sync.aligned.m8n8.x4.shared.b16 {%0,%1,%2,%3},[%4];"
                 : "=r"(r0), "=r"(r1), "=r"(r2), "=r"(r3) : "r"(a));
}
__device__ __forceinline__ void mma_bf16(float& d0, float& d1, float& d2, float& d3,
                                         unsigned a0, unsigned a1, unsigned a2, unsigned a3,
                                         unsigned b0, unsigned b1) {
    asm volatile("mma.sync.aligned.m16n8k16.row.col.f32.bf16.bf16.f32 "
                 "{%0,%1,%2,%3},{%4,%5,%6,%7},{%8,%9},{%0,%1,%2,%3};"
                 : "+f"(d0), "+f"(d1), "+f"(d2), "+f"(d3)
                 : "r"(a0), "r"(a1), "r"(a2), "r"(a3), "r"(b0), "r"(b1));
}

__global__ void init_ctr_kernel() {
#pragma unroll
    for (int i = 0; i < 4; ++i)
        g_ctr2[threadIdx.x + i * 512] = 0u;
}

// ---------------------------------------------------------------------------
// fp32 -> bf16 hi/lo split with zero k-padding.
// ---------------------------------------------------------------------------
__global__ void cvt_split_kernel(int sel, const float* __restrict__ src) {
    int rows, ks, kd;
    unsigned short *dh, *dl;
    if (sel == 0)      { rows = V_;  ks = E_; kd = EP_; dh = g_embh; dl = g_embl; }
    else if (sel == 1) { rows = G3H; ks = E_; kd = EP_; dh = g_w0h;  dl = g_w0l; }
    else               { rows = G3H; ks = H_; kd = H_;  dh = g_w1h;  dl = g_w1l; }

    size_t tot = (size_t)rows * kd;
    for (size_t idx = blockIdx.x * blockDim.x + threadIdx.x; idx < tot;
         idx += (size_t)gridDim.x * blockDim.x) {
        int r = (int)(idx / kd);
        int c = (int)(idx - (size_t)r * kd);
        float v = (c < ks) ? src[(size_t)r * ks + c] : 0.f;
        unsigned h = bf16_bits(v);
        float rem = v - bf16_val(h);
        dh[idx] = (unsigned short)h;
        dl[idx] = (unsigned short)bf16_bits(rem);
    }
}

// ---------------------------------------------------------------------------
// Tensor-core projection GEMM (mma.sync, unchanged from R8 — proven)
// ---------------------------------------------------------------------------
#define PROW 24
#define PMAT 6144
#define PSTG 24576
#define SMEM_PROJ (2 * PSTG)

template <int K, int SRC>
__global__ __launch_bounds__(256, 1) void proj_mma(
    const int* __restrict__ gidx, const float* __restrict__ bias)
{
    extern __shared__ __align__(16) char smp[];
    const unsigned short* Ah = (SRC == 0) ? g_embh : g_hbh;
    const unsigned short* Al = (SRC == 0) ? g_embl : g_hbl;
    const unsigned short* Wh = (SRC == 0) ? g_w0h : g_w1h;
    const unsigned short* Wl = (SRC == 0) ? g_w0l : g_w1l;
    float* C = (SRC == 0) ? g_xp0 : g_xp1;

    const int tid = threadIdx.x;
    const int li  = tid & 31;
    const int w   = tid >> 5;
    const int wm  = w >> 1;
    const int wn  = w & 1;
    const int m0  = blockIdx.y * 128;
    const int n0  = blockIdx.x * 128;
    const unsigned sbase = smem_u32(smp);

    const int lrow  = tid >> 1;
    const int lhalf = tid & 1;
    size_t arow;
    if (SRC == 0) arow = (size_t)__ldg(gidx + m0 + lrow) * K;
    else          arow = (size_t)(m0 + lrow) * K;
    const size_t brow = (size_t)(n0 + lrow) * K;
    const unsigned sst = (unsigned)(lrow * PROW + lhalf * 8) * 2;

    float acc[2][8][4];
#pragma unroll
    for (int a = 0; a < 2; ++a)
#pragma unroll
        for (int b = 0; b < 8; ++b)
#pragma unroll
            for (int c = 0; c < 4; ++c) acc[a][b][c] = 0.f;

    const int KT = K / 16;
    uint4 rAh, rAl, rBh, rBl;
    {
        const int k0 = lhalf * 8;
        rAh = *(const uint4*)(Ah + arow + k0);
        rAl = *(const uint4*)(Al + arow + k0);
        rBh = *(const uint4*)(Wh + brow + k0);
        rBl = *(const uint4*)(Wl + brow + k0);
        *(uint4*)(smp + 0 * PMAT + sst) = rAh;
        *(uint4*)(smp + 1 * PMAT + sst) = rAl;
        *(uint4*)(smp + 2 * PMAT + sst) = rBh;
        *(uint4*)(smp + 3 * PMAT + sst) = rBl;
    }
    __syncthreads();

    const unsigned aoff = (unsigned)((wm * 32 + (li & 15)) * PROW + (li >> 4) * 8) * 2;
    const unsigned boff = (unsigned)((wn * 64 + (li & 15)) * PROW + (li >> 4) * 8) * 2;

    for (int kt = 0; kt < KT; ++kt) {
        const unsigned sb0 = sbase + (unsigned)(kt & 1) * PSTG;
        if (kt + 1 < KT) {
            const int k0 = (kt + 1) * 16 + lhalf * 8;
            rAh = *(const uint4*)(Ah + arow + k0);
            rAl = *(const uint4*)(Al + arow + k0);
            rBh = *(const uint4*)(Wh + brow + k0);
            rBl = *(const uint4*)(Wl + brow + k0);
        }

        unsigned aH[2][4], aL[2][4];
#pragma unroll
        for (int mt = 0; mt < 2; ++mt) {
            ldsm_x4(aH[mt][0], aH[mt][1], aH[mt][2], aH[mt][3],
                    sb0 + 0 * PMAT + aoff + mt * 768);
            ldsm_x4(aL[mt][0], aL[mt][1], aL[mt][2], aL[mt][3],
                    sb0 + 1 * PMAT + aoff + mt * 768);
        }
#pragma unroll
        for (int ng = 0; ng < 4; ++ng) {
            unsigned bh[4], bl[4];
            ldsm_x4(bh[0], bh[1], bh[2], bh[3], sb0 + 2 * PMAT + boff + ng * 768);
            ldsm_x4(bl[0], bl[1], bl[2], bl[3], sb0 + 3 * PMAT + boff + ng * 768);
#pragma unroll
            for (int mt = 0; mt < 2; ++mt) {
                float* d0 = acc[mt][2 * ng];
                mma_bf16(d0[0], d0[1], d0[2], d0[3],
                         aH[mt][0], aH[mt][1], aH[mt][2], aH[mt][3], bh[0], bh[2]);
                mma_bf16(d0[0], d0[1], d0[2], d0[3],
                         aH[mt][0], aH[mt][1], aH[mt][2], aH[mt][3], bl[0], bl[2]);
                mma_bf16(d0[0], d0[1], d0[2], d0[3],
                         aL[mt][0], aL[mt][1], aL[mt][2], aL[mt][3], bh[0], bh[2]);
                float* d1 = acc[mt][2 * ng + 1];
                mma_bf16(d1[0], d1[1], d1[2], d1[3],
                         aH[mt][0], aH[mt][1], aH[mt][2], aH[mt][3], bh[1], bh[3]);
                mma_bf16(d1[0], d1[1], d1[2], d1[3],
                         aH[mt][0], aH[mt][1], aH[mt][2], aH[mt][3], bl[1], bl[3]);
                mma_bf16(d1[0], d1[1], d1[2], d1[3],
                         aL[mt][0], aL[mt][1], aL[mt][2], aL[mt][3], bh[1], bh[3]);
            }
        }
        if (kt + 1 < KT) {
            char* nb = smp + ((kt & 1) ^ 1) * PSTG;
            *(uint4*)(nb + 0 * PMAT + sst) = rAh;
            *(uint4*)(nb + 1 * PMAT + sst) = rAl;
            *(uint4*)(nb + 2 * PMAT + sst) = rBh;
            *(uint4*)(nb + 3 * PMAT + sst) = rBl;
            __syncthreads();
        }
    }

    const int fg = li >> 2;
    const int ft = li & 3;
#pragma unroll
    for (int mt = 0; mt < 2; ++mt) {
#pragma unroll
        for (int nt = 0; nt < 8; ++nt) {
            const int row = m0 + wm * 32 + mt * 16 + fg;
            const int col = n0 + wn * 64 + nt * 8 + 2 * ft;
            const float b0 = __ldg(bias + col);
            const float b1 = __ldg(bias + col + 1);
            float* c0 = C + (size_t)row * G3H + col;
            float* c1 = C + (size_t)(row + 8) * G3H + col;
            *(float2*)c0 = make_float2(acc[mt][nt][0] + b0, acc[mt][nt][1] + b1);
            *(float2*)c1 = make_float2(acc[mt][nt][2] + b0, acc[mt][nt][3] + b1);
        }
    }
}

// ---------------------------------------------------------------------------
// Persistent GRU recurrence — mma.sync with A-hi fragments REGISTER-RESIDENT.
// 128 CTAs = 8 groups x 16; CTA gidx owns hidden slice [gidx*32,+32).
// Warp (mt, kh): A-hi frags for its 16x256 slice live in regs all 512 steps.
// Per step: 8 x ldsm_x4 (A-lo pairs) + 8 x ldsm_x4 (B hi) + 8 (B lo? no:
// pairs carry both ks) -> 16 ldsm_x4 total + 48 HMMA per warp.
// ---------------------------------------------------------------------------
#define WROW    520
#define WH_OFF  0
#define WL_OFF  99840
#define HH_OFF  199680
#define HL_OFF  208000
#define RED_OFF 216320
#define SB_OFF  223232
#define SMEM_REC_BYTES 223616

__global__ __launch_bounds__(384, 1) void rec_kernel(
    const float* __restrict__ Whh, const float* __restrict__ bhh, int layer)
{
    extern __shared__ char smc[];
    float* red = (float*)(smc + RED_OFF);
    float* sb  = (float*)(smc + SB_OFF);
    const unsigned sbase = smem_u32(smc);

    const float* xp = layer ? g_xp1 : g_xp0;

    const int tid   = threadIdx.x;
    const int wid   = tid >> 5;
    const int li    = tid & 31;
    const int bid   = blockIdx.x;
    const int group = bid >> 4;
    const int gidx  = bid & 15;
    const int rb    = group * 8;
    const int ibase = gidx * 32;
    unsigned* ctr = g_ctr2 + (layer * 8 + group) * 32;

    unsigned short* hbh = g_hbh + (size_t)layer * M_ * H_;
    unsigned short* hbl = g_hbl + (size_t)layer * M_ * H_;

    // ---- preload weights (bf16 hi/lo split) + bias ----
    for (int idx = tid; idx < 96 * 256; idx += 384) {
        int r  = idx >> 8;
        int kk = (idx & 255) << 1;
        int gr = (r >> 5) * 512 + ibase + (r & 31);
        float2 wv = *(const float2*)(Whh + (size_t)gr * 512 + kk);
        unsigned h0 = bf16_bits(wv.x), h1 = bf16_bits(wv.y);
        unsigned l0 = bf16_bits(wv.x - bf16_val(h0));
        unsigned l1 = bf16_bits(wv.y - bf16_val(h1));
        *(unsigned*)(smc + WH_OFF + (r * WROW + kk) * 2) = (h1 << 16) | h0;
        *(unsigned*)(smc + WL_OFF + (r * WROW + kk) * 2) = (l1 << 16) | l0;
    }
    if (tid < 96) {
        int gr = (tid >> 5) * 512 + ibase + (tid & 31);
        sb[tid] = __ldg(bhh + gr);
    }
    __syncthreads();

    // MMA warp roles
    const int mt = wid % 6;
    const int kh = wid / 6;                // 0/1 (wid < 12)
    const int k0 = kh * 256;
    const int la = li & 15;
    const unsigned aoff = ((mt * 16 + la) * WROW + k0 + ((li >> 4) & 1) * 8) * 2;
    const unsigned aAhi = sbase + WH_OFF + aoff;
    const unsigned aAlo = sbase + WL_OFF + aoff;
    // B paired x4 address: lanes 0-7 -> col +0, 8-15 -> +8, 16-23 -> +16, 24-31 -> +24
    const unsigned boff4 = (((li & 7) * WROW) + k0 + ((li >> 3) & 3) * 8) * 2;
    const unsigned aBhi = sbase + HH_OFF + boff4;
    const unsigned aBlo = sbase + HL_OFF + boff4;
    const int fg = li >> 2;
    const int ft = li & 3;
    const int eb = tid >> 5;
    const int ei = tid & 31;

    // ---- A-hi fragments: register-resident for the whole kernel ----
    unsigned aH[16][4];
    if (wid < 12) {
#pragma unroll
        for (int ks = 0; ks < 16; ++ks)
            ldsm_x4(aH[ks][0], aH[ks][1], aH[ks][2], aH[ks][3], aAhi + ks * 32);
    }

    float h_prev_reg = 0.f;

    for (int t = 0; t < T_; ++t) {
        // ---- xp prefetch (overlaps poll) ----
        float xr = 0.f, xz = 0.f, xn = 0.f;
        if (tid < 256) {
            const float* xrow = xp + ((size_t)t * B_ + rb + eb) * G3H + ibase + ei;
            xr = __ldg(xrow);
            xz = __ldg(xrow + 512);
            xn = __ldg(xrow + 1024);
        }

        // ---- single-thread poll, bar broadcast, then stage ----
        if (t == 0) {
            for (int idx = tid; idx < 2048; idx += 384) {
                int b = idx >> 8, kk = (idx & 255) << 1;
                *(unsigned*)(smc + HH_OFF + (b * WROW + kk) * 2) = 0u;
                *(unsigned*)(smc + HL_OFF + (b * WROW + kk) * 2) = 0u;
            }
        } else {
            if (tid == 0) {
                unsigned target = 16u * (unsigned)t;
                while (ld_acquire(ctr) < target) { }
            }
            __syncthreads();
            const size_t base = ((size_t)(t - 1) * B_ + rb) * H_;
            for (int idx = tid; idx < 2048; idx += 384) {
                int b = idx >> 8, kk = (idx & 255) << 1;
                unsigned vh = __ldcg((const unsigned*)(hbh + base + (size_t)b * H_ + kk));
                unsigned vl = __ldcg((const unsigned*)(hbl + base + (size_t)b * H_ + kk));
                *(unsigned*)(smc + HH_OFF + (b * WROW + kk) * 2) = vh;
                *(unsigned*)(smc + HL_OFF + (b * WROW + kk) * 2) = vl;
            }
        }
        __syncthreads();

        // ---- tensor-core matvec: warps 0-11 ----
        if (wid < 12) {
            float d0[4] = {0.f, 0.f, 0.f, 0.f};
            float d1[4] = {0.f, 0.f, 0.f, 0.f};
#pragma unroll
            for (int ps = 0; ps < 8; ++ps) {
                const unsigned pb = ps * 64;          // 32 k = 64 B
                unsigned bh[4], bl[4], al0[4], al1[4];
                ldsm_x4(bh[0], bh[1], bh[2], bh[3], aBhi + pb);
                ldsm_x4(bl[0], bl[1], bl[2], bl[3], aBlo + pb);
                ldsm_x4(al0[0], al0[1], al0[2], al0[3], aAlo + (2 * ps) * 32);
                ldsm_x4(al1[0], al1[1], al1[2], al1[3], aAlo + (2 * ps + 1) * 32);
                const unsigned* a0 = aH[2 * ps];
                const unsigned* a1 = aH[2 * ps + 1];
                mma_bf16(d0[0], d0[1], d0[2], d0[3],
                         a0[0], a0[1], a0[2], a0[3], bh[0], bh[1]);
                mma_bf16(d0[0], d0[1], d0[2], d0[3],
                         a0[0], a0[1], a0[2], a0[3], bl[0], bl[1]);
                mma_bf16(d0[0], d0[1], d0[2], d0[3],
                         al0[0], al0[1], al0[2], al0[3], bh[0], bh[1]);
                mma_bf16(d1[0], d1[1], d1[2], d1[3],
                         a1[0], a1[1], a1[2], a1[3], bh[2], bh[3]);
                mma_bf16(d1[0], d1[1], d1[2], d1[3],
                         a1[0], a1[1], a1[2], a1[3], bl[2], bl[3]);
                mma_bf16(d1[0], d1[1], d1[2], d1[3],
                         al1[0], al1[1], al1[2], al1[3], bh[2], bh[3]);
            }
            float* rk = red + kh * 96 * 9;
            rk[(mt * 16 + fg)     * 9 + 2 * ft    ] = d0[0] + d1[0];
            rk[(mt * 16 + fg)     * 9 + 2 * ft + 1] = d0[1] + d1[1];
            rk[(mt * 16 + fg + 8) * 9 + 2 * ft    ] = d0[2] + d1[2];
            rk[(mt * 16 + fg + 8) * 9 + 2 * ft + 1] = d0[3] + d1[3];
        }
        __syncthreads();

        // ---- elementwise (threads 0-255) ----
        if (tid < 256) {
            float ghr = red[(ei) * 9 + eb]      + red[96 * 9 + (ei) * 9 + eb];
            float ghz = red[(32 + ei) * 9 + eb] + red[96 * 9 + (32 + ei) * 9 + eb];
            float ghn = red[(64 + ei) * 9 + eb] + red[96 * 9 + (64 + ei) * 9 + eb];
            ghr += sb[ei];
            ghz += sb[32 + ei];
            ghn += sb[64 + ei];

            float r = sigmoidf_(xr + ghr);
            float z = sigmoidf_(xz + ghz);
            float n = tanhf_(xn + r * ghn);
            float hnew = n + z * (h_prev_reg - n);
            h_prev_reg = hnew;

            const size_t off = ((size_t)t * B_ + rb + eb) * H_ + ibase + ei;
            unsigned hb = bf16_bits(hnew);
            float rem = hnew - bf16_val(hb);
            hbh[off] = (unsigned short)hb;
            hbl[off] = (unsigned short)bf16_bits(rem);
            if (layer) __stcg(g_h2 + off, hnew);
        }

        // ---- release ----
        __syncthreads();
        if (tid == 0) red_release(ctr, 1u);
    }
}

// ---------------------------------------------------------------------------
// Pool over batch + FC
// ---------------------------------------------------------------------------
__global__ __launch_bounds__(256) void pool_fc_kernel(
    const float* __restrict__ fcW, const float* __restrict__ fcb,
    float* __restrict__ out)
{
    __shared__ float rbuf[5][256];
    const int t = blockIdx.x;
    const int tid = threadIdx.x;

    float s0 = 0.f, s1 = 0.f;
    const float* base = g_h2 + (size_t)t * B_ * H_ + tid * 2;
#pragma unroll 8
    for (int b = 0; b < B_; ++b) {
        float2 vv = *(const float2*)(base + (size_t)b * H_);
        s0 += vv.x; s1 += vv.y;
    }
    s0 *= (1.0f / 64.0f);
    s1 *= (1.0f / 64.0f);

#pragma unroll
    for (int l = 0; l < L_; ++l)
        rbuf[l][tid] = s0 * __ldg(fcW + l * H_ + tid * 2)
                     + s1 * __ldg(fcW + l * H_ + tid * 2 + 1);
    __syncthreads();

    for (int s = 128; s > 0; s >>= 1) {
        if (tid < s) {
#pragma unroll
            for (int l = 0; l < L_; ++l) rbuf[l][tid] += rbuf[l][tid + s];
        }
        __syncthreads();
    }
    if (tid < L_) out[t * L_ + tid] = rbuf[tid][0] + __ldg(fcb + tid);
}

// ---------------------------------------------------------------------------
// launcher
// ---------------------------------------------------------------------------
extern "C" void kernel_launch(void* const* d_in, const int* in_sizes, int n_in,
                              void* d_out, int out_size) {
    (void)in_sizes; (void)n_in; (void)out_size;
    const int*   texts = (const int*)  d_in[0];
    const float* emb   = (const float*)d_in[1];
    const float* Wih0  = (const float*)d_in[2];
    const float* Whh0  = (const float*)d_in[3];
    const float* bih0  = (const float*)d_in[4];
    const float* bhh0  = (const float*)d_in[5];
    const float* Wih1  = (const float*)d_in[6];
    const float* Whh1  = (const float*)d_in[7];
    const float* bih1  = (const float*)d_in[8];
    const float* bhh1  = (const float*)d_in[9];
    const float* fcW   = (const float*)d_in[10];
    const float* fcb   = (const float*)d_in[11];
    float* out = (float*)d_out;

    cudaFuncSetAttribute(rec_kernel,
                         cudaFuncAttributeMaxDynamicSharedMemorySize,
                         SMEM_REC_BYTES);
    cudaFuncSetAttribute(proj_mma<EP_, 0>,
                         cudaFuncAttributeMaxDynamicSharedMemorySize, SMEM_PROJ);
    cudaFuncSetAttribute(proj_mma<H_, 1>,
                         cudaFuncAttributeMaxDynamicSharedMemorySize, SMEM_PROJ);

    init_ctr_kernel<<<1, 512>>>();
    cvt_split_kernel<<<2048, 256>>>(0, emb);
    cvt_split_kernel<<<512, 256>>>(1, Wih0);
    cvt_split_kernel<<<512, 256>>>(2, Wih1);
    proj_mma<EP_, 0><<<dim3(12, 256), 256, SMEM_PROJ>>>(texts, bih0);
    rec_kernel<<<128, 384, SMEM_REC_BYTES>>>(Whh0, bhh0, 0);
    proj_mma<H_, 1><<<dim3(12, 256), 256, SMEM_PROJ>>>(nullptr, bih1);
    rec_kernel<<<128, 384, SMEM_REC_BYTES>>>(Whh1, bhh1, 1);
    pool_fc_kernel<<<512, 256>>>(fcW, fcb, out);
}

// round 11
// speedup vs baseline: 1.7012x; 1.1561x over previous
#include <cuda_runtime.h>
#include <cuda_bf16.h>
#include <math.h>
#include <stdint.h>

// Problem dims
#define T_  512
#define B_  64
#define E_  300
#define H_  512
#define L_  5
#define G3H 1536
#define M_  (T_*B_)          // 32768
#define V_  30000
#define EP_ 304              // E padded to k16 multiple

// ---------------------------------------------------------------------------
// Scratch (device globals — no runtime allocation allowed)
// ---------------------------------------------------------------------------
__device__ float g_xp0[(size_t)M_ * G3H];
__device__ float g_xp1[(size_t)M_ * G3H];
__device__ float g_h2 [(size_t)M_ * H_];
__device__ unsigned g_ctr2[2048];
// bf16 hi/lo split operands
__device__ unsigned short g_embh[(size_t)V_ * EP_];
__device__ unsigned short g_embl[(size_t)V_ * EP_];
__device__ unsigned short g_w0h[(size_t)G3H * EP_];
__device__ unsigned short g_w0l[(size_t)G3H * EP_];
__device__ unsigned short g_w1h[(size_t)G3H * H_];
__device__ unsigned short g_w1l[(size_t)G3H * H_];
__device__ unsigned short g_hbh[2 * (size_t)M_ * H_];
__device__ unsigned short g_hbl[2 * (size_t)M_ * H_];

// ---------------------------------------------------------------------------
// helpers
// ---------------------------------------------------------------------------
__device__ __forceinline__ unsigned ld_acquire(const unsigned* p) {
    unsigned v;
    asm volatile("ld.acquire.gpu.u32 %0, [%1];" : "=r"(v) : "l"(p) : "memory");
    return v;
}
__device__ __forceinline__ void red_release(unsigned* p, unsigned v) {
    asm volatile("red.release.gpu.global.add.u32 [%0], %1;" :: "l"(p), "r"(v) : "memory");
}
__device__ __forceinline__ float sigmoidf_(float x) {
    return 1.0f / (1.0f + __expf(-x));
}
__device__ __forceinline__ float tanhf_(float x) {
    return 1.0f - 2.0f / (__expf(2.0f * x) + 1.0f);
}
__device__ __forceinline__ unsigned smem_u32(const void* p) {
    unsigned a;
    asm("{ .reg .u64 t; cvta.to.shared.u64 t, %1; cvt.u32.u64 %0, t; }"
        : "=r"(a) : "l"(p));
    return a;
}
__device__ __forceinline__ unsigned bf16_bits(float x) {
    __nv_bfloat16 h = __float2bfloat16_rn(x);
    return (unsigned)(reinterpret_cast<__nv_bfloat16_raw&>(h).x);
}
__device__ __forceinline__ float bf16_val(unsigned bits) {
    __nv_bfloat16_raw r; r.x = (unsigned short)bits;
    return __bfloat162float(reinterpret_cast<__nv_bfloat16&>(r));
}
__device__ __forceinline__ void ldsm_x4(unsigned& r0, unsigned& r1,
                                        unsigned& r2, unsigned& r3, unsigned a) {
    asm volatile("ldmatrix.sync.aligned.m8n8.x4.shared.b16 {%0,%1,%2,%3},[%4];"
                 : "=r"(r0), "=r"(r1), "=r"(r2), "=r"(r3) : "r"(a));
}
__device__ __forceinline__ void mma_bf16(float& d0, float& d1, float& d2, float& d3,
                                         unsigned a0, unsigned a1, unsigned a2, unsigned a3,
                                         unsigned b0, unsigned b1) {
    asm volatile("mma.sync.aligned.m16n8k16.row.col.f32.bf16.bf16.f32 "
                 "{%0,%1,%2,%3},{%4,%5,%6,%7},{%8,%9},{%0,%1,%2,%3};"
                 : "+f"(d0), "+f"(d1), "+f"(d2), "+f"(d3)
                 : "r"(a0), "r"(a1), "r"(a2), "r"(a3), "r"(b0), "r"(b1));
}

__global__ void init_ctr_kernel() {
#pragma unroll
    for (int i = 0; i < 4; ++i)
        g_ctr2[threadIdx.x + i * 512] = 0u;
}

// ---------------------------------------------------------------------------
// Merged fp32 -> bf16 hi/lo split (emb + Wih0 + Wih1 in one launch).
// ---------------------------------------------------------------------------
__global__ void cvt_all_kernel(const float* __restrict__ emb,
                               const float* __restrict__ w0,
                               const float* __restrict__ w1) {
    const size_t N0 = (size_t)V_ * EP_;
    const size_t N1 = N0 + (size_t)G3H * EP_;
    const size_t N2 = N1 + (size_t)G3H * H_;
    for (size_t i = (size_t)blockIdx.x * blockDim.x + threadIdx.x; i < N2;
         i += (size_t)gridDim.x * blockDim.x) {
        const float* src; int ks, kd; size_t idx;
        unsigned short *dh, *dl;
        if (i < N0)      { src = emb; ks = E_; kd = EP_; idx = i;      dh = g_embh; dl = g_embl; }
        else if (i < N1) { src = w0;  ks = E_; kd = EP_; idx = i - N0; dh = g_w0h;  dl = g_w0l; }
        else             { src = w1;  ks = H_; kd = H_;  idx = i - N1; dh = g_w1h;  dl = g_w1l; }
        int r = (int)(idx / kd);
        int c = (int)(idx - (size_t)r * kd);
        float v = (c < ks) ? src[(size_t)r * ks + c] : 0.f;
        unsigned h = bf16_bits(v);
        dh[idx] = (unsigned short)h;
        dl[idx] = (unsigned short)bf16_bits(v - bf16_val(h));
    }
}

// ---------------------------------------------------------------------------
// Tensor-core projection GEMM (mma.sync, unchanged — proven)
// ---------------------------------------------------------------------------
#define PROW 24
#define PMAT 6144
#define PSTG 24576
#define SMEM_PROJ (2 * PSTG)

template <int K, int SRC>
__global__ __launch_bounds__(256, 1) void proj_mma(
    const int* __restrict__ gidx, const float* __restrict__ bias)
{
    extern __shared__ __align__(16) char smp[];
    const unsigned short* Ah = (SRC == 0) ? g_embh : g_hbh;
    const unsigned short* Al = (SRC == 0) ? g_embl : g_hbl;
    const unsigned short* Wh = (SRC == 0) ? g_w0h : g_w1h;
    const unsigned short* Wl = (SRC == 0) ? g_w0l : g_w1l;
    float* C = (SRC == 0) ? g_xp0 : g_xp1;

    const int tid = threadIdx.x;
    const int li  = tid & 31;
    const int w   = tid >> 5;
    const int wm  = w >> 1;
    const int wn  = w & 1;
    const int m0  = blockIdx.y * 128;
    const int n0  = blockIdx.x * 128;
    const unsigned sbase = smem_u32(smp);

    const int lrow  = tid >> 1;
    const int lhalf = tid & 1;
    size_t arow;
    if (SRC == 0) arow = (size_t)__ldg(gidx + m0 + lrow) * K;
    else          arow = (size_t)(m0 + lrow) * K;
    const size_t brow = (size_t)(n0 + lrow) * K;
    const unsigned sst = (unsigned)(lrow * PROW + lhalf * 8) * 2;

    float acc[2][8][4];
#pragma unroll
    for (int a = 0; a < 2; ++a)
#pragma unroll
        for (int b = 0; b < 8; ++b)
#pragma unroll
            for (int c = 0; c < 4; ++c) acc[a][b][c] = 0.f;

    const int KT = K / 16;
    uint4 rAh, rAl, rBh, rBl;
    {
        const int k0 = lhalf * 8;
        rAh = *(const uint4*)(Ah + arow + k0);
        rAl = *(const uint4*)(Al + arow + k0);
        rBh = *(const uint4*)(Wh + brow + k0);
        rBl = *(const uint4*)(Wl + brow + k0);
        *(uint4*)(smp + 0 * PMAT + sst) = rAh;
        *(uint4*)(smp + 1 * PMAT + sst) = rAl;
        *(uint4*)(smp + 2 * PMAT + sst) = rBh;
        *(uint4*)(smp + 3 * PMAT + sst) = rBl;
    }
    __syncthreads();

    const unsigned aoff = (unsigned)((wm * 32 + (li & 15)) * PROW + (li >> 4) * 8) * 2;
    const unsigned boff = (unsigned)((wn * 64 + (li & 15)) * PROW + (li >> 4) * 8) * 2;

    for (int kt = 0; kt < KT; ++kt) {
        const unsigned sb0 = sbase + (unsigned)(kt & 1) * PSTG;
        if (kt + 1 < KT) {
            const int k0 = (kt + 1) * 16 + lhalf * 8;
            rAh = *(const uint4*)(Ah + arow + k0);
            rAl = *(const uint4*)(Al + arow + k0);
            rBh = *(const uint4*)(Wh + brow + k0);
            rBl = *(const uint4*)(Wl + brow + k0);
        }

        unsigned aH[2][4], aL[2][4];
#pragma unroll
        for (int mt = 0; mt < 2; ++mt) {
            ldsm_x4(aH[mt][0], aH[mt][1], aH[mt][2], aH[mt][3],
                    sb0 + 0 * PMAT + aoff + mt * 768);
            ldsm_x4(aL[mt][0], aL[mt][1], aL[mt][2], aL[mt][3],
                    sb0 + 1 * PMAT + aoff + mt * 768);
        }
#pragma unroll
        for (int ng = 0; ng < 4; ++ng) {
            unsigned bh[4], bl[4];
            ldsm_x4(bh[0], bh[1], bh[2], bh[3], sb0 + 2 * PMAT + boff + ng * 768);
            ldsm_x4(bl[0], bl[1], bl[2], bl[3], sb0 + 3 * PMAT + boff + ng * 768);
#pragma unroll
            for (int mt = 0; mt < 2; ++mt) {
                float* d0 = acc[mt][2 * ng];
                mma_bf16(d0[0], d0[1], d0[2], d0[3],
                         aH[mt][0], aH[mt][1], aH[mt][2], aH[mt][3], bh[0], bh[2]);
                mma_bf16(d0[0], d0[1], d0[2], d0[3],
                         aH[mt][0], aH[mt][1], aH[mt][2], aH[mt][3], bl[0], bl[2]);
                mma_bf16(d0[0], d0[1], d0[2], d0[3],
                         aL[mt][0], aL[mt][1], aL[mt][2], aL[mt][3], bh[0], bh[2]);
                float* d1 = acc[mt][2 * ng + 1];
                mma_bf16(d1[0], d1[1], d1[2], d1[3],
                         aH[mt][0], aH[mt][1], aH[mt][2], aH[mt][3], bh[1], bh[3]);
                mma_bf16(d1[0], d1[1], d1[2], d1[3],
                         aH[mt][0], aH[mt][1], aH[mt][2], aH[mt][3], bl[1], bl[3]);
                mma_bf16(d1[0], d1[1], d1[2], d1[3],
                         aL[mt][0], aL[mt][1], aL[mt][2], aL[mt][3], bh[1], bh[3]);
            }
        }
        if (kt + 1 < KT) {
            char* nb = smp + ((kt & 1) ^ 1) * PSTG;
            *(uint4*)(nb + 0 * PMAT + sst) = rAh;
            *(uint4*)(nb + 1 * PMAT + sst) = rAl;
            *(uint4*)(nb + 2 * PMAT + sst) = rBh;
            *(uint4*)(nb + 3 * PMAT + sst) = rBl;
            __syncthreads();
        }
    }

    const int fg = li >> 2;
    const int ft = li & 3;
#pragma unroll
    for (int mt = 0; mt < 2; ++mt) {
#pragma unroll
        for (int nt = 0; nt < 8; ++nt) {
            const int row = m0 + wm * 32 + mt * 16 + fg;
            const int col = n0 + wn * 64 + nt * 8 + 2 * ft;
            const float b0 = __ldg(bias + col);
            const float b1 = __ldg(bias + col + 1);
            float* c0 = C + (size_t)row * G3H + col;
            float* c1 = C + (size_t)(row + 8) * G3H + col;
            *(float2*)c0 = make_float2(acc[mt][nt][0] + b0, acc[mt][nt][1] + b1);
            *(float2*)c1 = make_float2(acc[mt][nt][2] + b0, acc[mt][nt][3] + b1);
        }
    }
}

// ---------------------------------------------------------------------------
// Persistent GRU recurrence — mma.sync, A-hi register-resident.
// Latency trims: per-warp poll, u64 staging, early release (named barrier).
// ---------------------------------------------------------------------------
#define WROW    520
#define WH_OFF  0
#define WL_OFF  99840
#define HH_OFF  199680
#define HL_OFF  208000
#define RED_OFF 216320
#define SB_OFF  223232
#define SMEM_REC_BYTES 223616

__global__ __launch_bounds__(384, 1) void rec_kernel(
    const float* __restrict__ Whh, const float* __restrict__ bhh, int layer)
{
    extern __shared__ char smc[];
    float* red = (float*)(smc + RED_OFF);
    float* sb  = (float*)(smc + SB_OFF);
    const unsigned sbase = smem_u32(smc);

    const float* xp = layer ? g_xp1 : g_xp0;

    const int tid   = threadIdx.x;
    const int wid   = tid >> 5;
    const int li    = tid & 31;
    const int bid   = blockIdx.x;
    const int group = bid >> 4;
    const int gidx  = bid & 15;
    const int rb    = group * 8;
    const int ibase = gidx * 32;
    unsigned* ctr = g_ctr2 + (layer * 8 + group) * 32;

    unsigned short* hbh = g_hbh + (size_t)layer * M_ * H_;
    unsigned short* hbl = g_hbl + (size_t)layer * M_ * H_;

    // ---- preload weights (bf16 hi/lo split) + bias ----
    for (int idx = tid; idx < 96 * 256; idx += 384) {
        int r  = idx >> 8;
        int kk = (idx & 255) << 1;
        int gr = (r >> 5) * 512 + ibase + (r & 31);
        float2 wv = *(const float2*)(Whh + (size_t)gr * 512 + kk);
        unsigned h0 = bf16_bits(wv.x), h1 = bf16_bits(wv.y);
        unsigned l0 = bf16_bits(wv.x - bf16_val(h0));
        unsigned l1 = bf16_bits(wv.y - bf16_val(h1));
        *(unsigned*)(smc + WH_OFF + (r * WROW + kk) * 2) = (h1 << 16) | h0;
        *(unsigned*)(smc + WL_OFF + (r * WROW + kk) * 2) = (l1 << 16) | l0;
    }
    if (tid < 96) {
        int gr = (tid >> 5) * 512 + ibase + (tid & 31);
        sb[tid] = __ldg(bhh + gr);
    }
    __syncthreads();

    // MMA warp roles
    const int mt = wid % 6;
    const int kh = wid / 6;                // 0/1 (all 12 warps do MMA)
    const int k0 = kh * 256;
    const int la = li & 15;
    const unsigned aoff = ((mt * 16 + la) * WROW + k0 + ((li >> 4) & 1) * 8) * 2;
    const unsigned aAhi = sbase + WH_OFF + aoff;
    const unsigned aAlo = sbase + WL_OFF + aoff;
    const unsigned boff4 = (((li & 7) * WROW) + k0 + ((li >> 3) & 3) * 8) * 2;
    const unsigned aBhi = sbase + HH_OFF + boff4;
    const unsigned aBlo = sbase + HL_OFF + boff4;
    const int fg = li >> 2;
    const int ft = li & 3;
    const int eb = tid >> 5;
    const int ei = tid & 31;

    // ---- A-hi fragments: register-resident for the whole kernel ----
    unsigned aH[16][4];
#pragma unroll
    for (int ks = 0; ks < 16; ++ks)
        ldsm_x4(aH[ks][0], aH[ks][1], aH[ks][2], aH[ks][3], aAhi + ks * 32);

    float h_prev_reg = 0.f;

    for (int t = 0; t < T_; ++t) {
        // ---- xp prefetch (overlaps poll) ----
        float xr = 0.f, xz = 0.f, xn = 0.f;
        if (tid < 256) {
            const float* xrow = xp + ((size_t)t * B_ + rb + eb) * G3H + ibase + ei;
            xr = __ldg(xrow);
            xz = __ldg(xrow + 512);
            xn = __ldg(xrow + 1024);
        }

        // ---- per-warp poll + u64 staging ----
        if (t == 0) {
            for (int idx = tid; idx < 2048; idx += 384) {
                int b = idx >> 8, kk = (idx & 255) << 1;
                *(unsigned*)(smc + HH_OFF + (b * WROW + kk) * 2) = 0u;
                *(unsigned*)(smc + HL_OFF + (b * WROW + kk) * 2) = 0u;
            }
        } else {
            if (li == 0) {
                unsigned target = 16u * (unsigned)t;
                while (ld_acquire(ctr) < target) { }
            }
            __syncwarp();
            const size_t base = ((size_t)(t - 1) * B_ + rb) * H_;
            for (int idx = tid; idx < 1024; idx += 384) {
                int b = idx >> 7, kk = (idx & 127) << 2;
                unsigned long long vh = __ldcg(
                    (const unsigned long long*)(hbh + base + (size_t)b * H_ + kk));
                unsigned long long vl = __ldcg(
                    (const unsigned long long*)(hbl + base + (size_t)b * H_ + kk));
                *(unsigned long long*)(smc + HH_OFF + (b * WROW + kk) * 2) = vh;
                *(unsigned long long*)(smc + HL_OFF + (b * WROW + kk) * 2) = vl;
            }
        }
        __syncthreads();

        // ---- tensor-core matvec: all 12 warps ----
        {
            float d0[4] = {0.f, 0.f, 0.f, 0.f};
            float d1[4] = {0.f, 0.f, 0.f, 0.f};
#pragma unroll
            for (int ps = 0; ps < 8; ++ps) {
                const unsigned pb = ps * 64;
                unsigned bh[4], bl[4], al0[4], al1[4];
                ldsm_x4(bh[0], bh[1], bh[2], bh[3], aBhi + pb);
                ldsm_x4(bl[0], bl[1], bl[2], bl[3], aBlo + pb);
                ldsm_x4(al0[0], al0[1], al0[2], al0[3], aAlo + (2 * ps) * 32);
                ldsm_x4(al1[0], al1[1], al1[2], al1[3], aAlo + (2 * ps + 1) * 32);
                const unsigned* a0 = aH[2 * ps];
                const unsigned* a1 = aH[2 * ps + 1];
                mma_bf16(d0[0], d0[1], d0[2], d0[3],
                         a0[0], a0[1], a0[2], a0[3], bh[0], bh[1]);
                mma_bf16(d0[0], d0[1], d0[2], d0[3],
                         a0[0], a0[1], a0[2], a0[3], bl[0], bl[1]);
                mma_bf16(d0[0], d0[1], d0[2], d0[3],
                         al0[0], al0[1], al0[2], al0[3], bh[0], bh[1]);
                mma_bf16(d1[0], d1[1], d1[2], d1[3],
                         a1[0], a1[1], a1[2], a1[3], bh[2], bh[3]);
                mma_bf16(d1[0], d1[1], d1[2], d1[3],
                         a1[0], a1[1], a1[2], a1[3], bl[2], bl[3]);
                mma_bf16(d1[0], d1[1], d1[2], d1[3],
                         al1[0], al1[1], al1[2], al1[3], bh[2], bh[3]);
            }
            float* rk = red + kh * 96 * 9;
            rk[(mt * 16 + fg)     * 9 + 2 * ft    ] = d0[0] + d1[0];
            rk[(mt * 16 + fg)     * 9 + 2 * ft + 1] = d0[1] + d1[1];
            rk[(mt * 16 + fg + 8) * 9 + 2 * ft    ] = d0[2] + d1[2];
            rk[(mt * 16 + fg + 8) * 9 + 2 * ft + 1] = d0[3] + d1[3];
        }
        __syncthreads();

        // ---- elementwise (threads 0-255) + early release ----
        if (tid < 256) {
            float ghr = red[(ei) * 9 + eb]      + red[96 * 9 + (ei) * 9 + eb];
            float ghz = red[(32 + ei) * 9 + eb] + red[96 * 9 + (32 + ei) * 9 + eb];
            float ghn = red[(64 + ei) * 9 + eb] + red[96 * 9 + (64 + ei) * 9 + eb];
            ghr += sb[ei];
            ghz += sb[32 + ei];
            ghn += sb[64 + ei];

            float r = sigmoidf_(xr + ghr);
            float z = sigmoidf_(xz + ghz);
            float n = tanhf_(xn + r * ghn);
            float hnew = n + z * (h_prev_reg - n);
            h_prev_reg = hnew;

            const size_t off = ((size_t)t * B_ + rb + eb) * H_ + ibase + ei;
            unsigned hb = bf16_bits(hnew);
            float rem = hnew - bf16_val(hb);
            hbh[off] = (unsigned short)hb;
            hbl[off] = (unsigned short)bf16_bits(rem);
            if (layer) __stcg(g_h2 + off, hnew);

            asm volatile("bar.sync 1, 256;" ::: "memory");
            if (tid == 0) red_release(ctr, 1u);
        }
        // MMA-only warps (8-11) proceed to next-step staging; they self-block
        // on the poll (own release above is part of the 16-count target).
    }
}

// ---------------------------------------------------------------------------
// Pool over batch + FC
// ---------------------------------------------------------------------------
__global__ __launch_bounds__(256) void pool_fc_kernel(
    const float* __restrict__ fcW, const float* __restrict__ fcb,
    float* __restrict__ out)
{
    __shared__ float rbuf[5][256];
    const int t = blockIdx.x;
    const int tid = threadIdx.x;

    float s0 = 0.f, s1 = 0.f;
    const float* base = g_h2 + (size_t)t * B_ * H_ + tid * 2;
#pragma unroll 8
    for (int b = 0; b < B_; ++b) {
        float2 vv = *(const float2*)(base + (size_t)b * H_);
        s0 += vv.x; s1 += vv.y;
    }
    s0 *= (1.0f / 64.0f);
    s1 *= (1.0f / 64.0f);

#pragma unroll
    for (int l = 0; l < L_; ++l)
        rbuf[l][tid] = s0 * __ldg(fcW + l * H_ + tid * 2)
                     + s1 * __ldg(fcW + l * H_ + tid * 2 + 1);
    __syncthreads();

    for (int s = 128; s > 0; s >>= 1) {
        if (tid < s) {
#pragma unroll
            for (int l = 0; l < L_; ++l) rbuf[l][tid] += rbuf[l][tid + s];
        }
        __syncthreads();
    }
    if (tid < L_) out[t * L_ + tid] = rbuf[tid][0] + __ldg(fcb + tid);
}

// ---------------------------------------------------------------------------
// launcher
// ---------------------------------------------------------------------------
extern "C" void kernel_launch(void* const* d_in, const int* in_sizes, int n_in,
                              void* d_out, int out_size) {
    (void)in_sizes; (void)n_in; (void)out_size;
    const int*   texts = (const int*)  d_in[0];
    const float* emb   = (const float*)d_in[1];
    const float* Wih0  = (const float*)d_in[2];
    const float* Whh0  = (const float*)d_in[3];
    const float* bih0  = (const float*)d_in[4];
    const float* bhh0  = (const float*)d_in[5];
    const float* Wih1  = (const float*)d_in[6];
    const float* Whh1  = (const float*)d_in[7];
    const float* bih1  = (const float*)d_in[8];
    const float* bhh1  = (const float*)d_in[9];
    const float* fcW   = (const float*)d_in[10];
    const float* fcb   = (const float*)d_in[11];
    float* out = (float*)d_out;

    cudaFuncSetAttribute(rec_kernel,
                         cudaFuncAttributeMaxDynamicSharedMemorySize,
                         SMEM_REC_BYTES);
    cudaFuncSetAttribute(proj_mma<EP_, 0>,
                         cudaFuncAttributeMaxDynamicSharedMemorySize, SMEM_PROJ);
    cudaFuncSetAttribute(proj_mma<H_, 1>,
                         cudaFuncAttributeMaxDynamicSharedMemorySize, SMEM_PROJ);

    init_ctr_kernel<<<1, 512>>>();
    cvt_all_kernel<<<4096, 256>>>(emb, Wih0, Wih1);
    proj_mma<EP_, 0><<<dim3(12, 256), 256, SMEM_PROJ>>>(texts, bih0);
    rec_kernel<<<128, 384, SMEM_REC_BYTES>>>(Whh0, bhh0, 0);
    proj_mma<H_, 1><<<dim3(12, 256), 256, SMEM_PROJ>>>(nullptr, bih1);
    rec_kernel<<<128, 384, SMEM_REC_BYTES>>>(Whh1, bhh1, 1);
    pool_fc_kernel<<<512, 256>>>(fcW, fcb, out);
}